// round 1
// baseline (speedup 1.0000x reference)
#include <cuda_runtime.h>
#include <cuda_bf16.h>
#include <float.h>

#define NPTS 500
#define NP 8
#define NCOL 4000   // NPTS*NP

// ---------------- scratch (device globals; no allocs allowed) ----------------
__device__ int   g_inds[NCOL];       // knn(query=c, ref=ct) -> indices into ct
__device__ int   g_inds_tc[NCOL];    // knn(query=ct, ref=c) -> indices into c
__device__ float g_logit[2 * NCOL];  // [0:4000) dir0, [4000:8000) dir1
__device__ float g_w[2 * NCOL];      // softmax weights, same split
__device__ float g_cf_t[NPTS * 128]; // cloud_feat transposed [point][128]
__device__ float g_imf_t[NPTS * 32]; // img_feat transposed  [point][32]
__device__ float g_sf_t[NPTS * 128]; // sf  transposed [point][128]
__device__ float g_sfp_t[NPTS * 128];// sfp transposed [point][128]

__device__ __forceinline__ float lrelu(float x) { return x > 0.f ? x : 0.01f * x; }

// ---------------- Kernel A: dual-direction KNN (warp per query) ----------------
__global__ __launch_bounds__(256) void knn_kernel(const float* __restrict__ c,
                                                  const float* __restrict__ ct) {
    int gwarp = (blockIdx.x * blockDim.x + threadIdx.x) >> 5;
    int lane  = threadIdx.x & 31;
    if (gwarp >= 2 * NPTS) return;
    int dir = gwarp >= NPTS;
    int q   = dir ? gwarp - NPTS : gwarp;
    const float* Q = dir ? ct : c;
    const float* R = dir ? c  : ct;

    float qx = Q[q * 3 + 0], qy = Q[q * 3 + 1], qz = Q[q * 3 + 2];
    float qq = qx * qx + qy * qy + qz * qz;

    float bd[8]; int bi[8];
#pragma unroll
    for (int k = 0; k < 8; k++) { bd[k] = FLT_MAX; bi[k] = 0x3fffffff; }

    for (int j = lane; j < NPTS; j += 32) {
        float rx = R[j * 3 + 0], ry = R[j * 3 + 1], rz = R[j * 3 + 2];
        // same expansion as reference: |q|^2 - 2 q.r + |r|^2
        float d2 = qq - 2.f * (qx * rx + qy * ry + qz * rz) + (rx * rx + ry * ry + rz * rz);
        if (d2 < bd[7] || (d2 == bd[7] && j < bi[7])) {
            bd[7] = d2; bi[7] = j;
#pragma unroll
            for (int k = 7; k > 0; k--) {
                if (bd[k] < bd[k - 1] || (bd[k] == bd[k - 1] && bi[k] < bi[k - 1])) {
                    float td = bd[k]; bd[k] = bd[k - 1]; bd[k - 1] = td;
                    int   ti = bi[k]; bi[k] = bi[k - 1]; bi[k - 1] = ti;
                }
            }
        }
    }

    int*   outi = dir ? g_inds_tc : g_inds;
    float* outl = dir ? (g_logit + NCOL) : g_logit;

#pragma unroll
    for (int s = 0; s < NP; s++) {
        float md = bd[0]; int mi = bi[0];
#pragma unroll
        for (int off = 16; off; off >>= 1) {
            float od = __shfl_xor_sync(0xffffffffu, md, off);
            int   oi = __shfl_xor_sync(0xffffffffu, mi, off);
            if (od < md || (od == md && oi < mi)) { md = od; mi = oi; }
        }
        if (lane == 0) {
            outi[q * NP + s] = mi;
            // logit computed with direct differences, matching cur - sel_pts
            float dx = qx - R[mi * 3 + 0];
            float dy = qy - R[mi * 3 + 1];
            float dz = qz - R[mi * 3 + 2];
            outl[q * NP + s] = -sqrtf(dx * dx + dy * dy + dz * dz);
        }
        if (bi[0] == mi) {  // pop on owning lane
#pragma unroll
            for (int k = 0; k < 7; k++) { bd[k] = bd[k + 1]; bi[k] = bi[k + 1]; }
            bd[7] = FLT_MAX; bi[7] = 0x3fffffff;
        }
    }
}

// ---------------- Kernel B: global softmax over each 4000-vector ----------------
__global__ __launch_bounds__(256) void softmax_kernel() {
    int d = blockIdx.x;
    const float* x = g_logit + d * NCOL;
    float*       y = g_w + d * NCOL;
    __shared__ float red[256];
    int t = threadIdx.x;

    float m = -FLT_MAX;
    for (int i = t; i < NCOL; i += 256) m = fmaxf(m, x[i]);
    red[t] = m; __syncthreads();
    for (int s = 128; s; s >>= 1) { if (t < s) red[t] = fmaxf(red[t], red[t + s]); __syncthreads(); }
    m = red[0]; __syncthreads();

    float sum = 0.f;
    for (int i = t; i < NCOL; i += 256) sum += expf(x[i] - m);
    red[t] = sum; __syncthreads();
    for (int s = 128; s; s >>= 1) { if (t < s) red[t] += red[t + s]; __syncthreads(); }
    float inv = 1.f / red[0];

    for (int i = t; i < NCOL; i += 256) y[i] = expf(x[i] - m) * inv;
}

// ---------------- Kernel C: cloud_feat (3->64->128) + imf transpose ----------------
__global__ __launch_bounds__(128) void cf_kernel(const float* __restrict__ c,
                                                 const float* __restrict__ imf,
                                                 const float* __restrict__ wp1,
                                                 const float* __restrict__ bp1,
                                                 const float* __restrict__ wp2,
                                                 const float* __restrict__ bp2) {
    int t = threadIdx.x;
    if (blockIdx.x >= 125) {  // 4 blocks transpose img_feat (32 x 500)
        int base = (blockIdx.x - 125) * 4000;
        for (int i = t; i < 4000; i += 128) {
            int e = base + i;
            int ch = e / NPTS, p = e % NPTS;
            g_imf_t[p * 32 + ch] = imf[e];
        }
        return;
    }
    __shared__ float Hs[4][64];
    int p0 = blockIdx.x * 4;
    for (int e = t; e < 256; e += 128) {
        int lp = e >> 6, r = e & 63;
        int p = p0 + lp;
        float h = bp1[r] + wp1[r * 3] * c[p * 3] + wp1[r * 3 + 1] * c[p * 3 + 1] +
                  wp1[r * 3 + 2] * c[p * 3 + 2];
        Hs[lp][r] = lrelu(h);
    }
    __syncthreads();
    for (int e = t; e < 512; e += 128) {
        int lp = e >> 7, ch = e & 127;
        float s = bp2[ch];
        const float* wrow = wp2 + ch * 64;
#pragma unroll 8
        for (int k = 0; k < 64; k += 4) {
            float4 w4 = __ldg((const float4*)(wrow + k));
            s += w4.x * Hs[lp][k] + w4.y * Hs[lp][k + 1] + w4.z * Hs[lp][k + 2] + w4.w * Hs[lp][k + 3];
        }
        g_cf_t[(p0 + lp) * 128 + ch] = s;
    }
}

// ---------------- Kernel D: sf path (gather imf, 32->64->128, weight, mean) ----------------
// 4 points (32 cols) per block, 256 threads.
__global__ __launch_bounds__(256) void sf_kernel(const float* __restrict__ w1,
                                                 const float* __restrict__ b1,
                                                 const float* __restrict__ w2,
                                                 const float* __restrict__ b2) {
    __shared__ float W2s[128 * 64];   // 32 KB
    __shared__ float B2s[128];
    __shared__ float Xs[32][36];      // [col][k=32], padded
    __shared__ float Hs[32][68];      // [col][k=64], padded
    __shared__ float Wts[32];
    int t = threadIdx.x;
    int p0 = blockIdx.x * 4;

    for (int e = t; e < 2048; e += 256)
        *(float4*)&W2s[e * 4] = __ldg((const float4*)(w2 + e * 4));
    if (t < 128) B2s[t] = b2[t];
    if (t < 32)  Wts[t] = g_w[p0 * NP + t];
    {   // gather X: 32 cols x 8 float4 == 256 threads
        int col = t >> 3, f = t & 7;
        int p = p0 + (col >> 3);
        int nb = g_inds[p * NP + (col & 7)];
        *(float4*)&Xs[col][f * 4] = *(const float4*)&g_imf_t[nb * 32 + f * 4];
    }
    __syncthreads();

    {   // phase 2: H(64x32) = lrelu(W1 X + b1); tile 2 rows x 4 cols
        int r0 = (t >> 3) * 2, c0 = (t & 7) * 4;
        float acc[2][4] = {};
#pragma unroll
        for (int k = 0; k < 32; k += 4) {
            float4 xv[4];
#pragma unroll
            for (int cc = 0; cc < 4; cc++) xv[cc] = *(float4*)&Xs[c0 + cc][k];
#pragma unroll
            for (int rr = 0; rr < 2; rr++) {
                float4 wv = __ldg((const float4*)(w1 + (r0 + rr) * 32 + k));
#pragma unroll
                for (int cc = 0; cc < 4; cc++)
                    acc[rr][cc] += wv.x * xv[cc].x + wv.y * xv[cc].y + wv.z * xv[cc].z + wv.w * xv[cc].w;
            }
        }
#pragma unroll
        for (int rr = 0; rr < 2; rr++) {
            float b = __ldg(b1 + r0 + rr);
#pragma unroll
            for (int cc = 0; cc < 4; cc++)
                Hs[c0 + cc][r0 + rr] = lrelu(acc[rr][cc] + b);
        }
    }
    __syncthreads();

    {   // phase 3: Y(128x32) = W2 H; scale by softmax w; mean over 8 cols
        int r0 = (t >> 3) * 4, c0 = (t & 7) * 4;
        float acc[4][4] = {};
#pragma unroll
        for (int k = 0; k < 64; k += 4) {
            float4 xv[4];
#pragma unroll
            for (int cc = 0; cc < 4; cc++) xv[cc] = *(float4*)&Hs[c0 + cc][k];
#pragma unroll
            for (int rr = 0; rr < 4; rr++) {
                float4 wv = *(float4*)&W2s[(r0 + rr) * 64 + k];
#pragma unroll
                for (int cc = 0; cc < 4; cc++)
                    acc[rr][cc] += wv.x * xv[cc].x + wv.y * xv[cc].y + wv.z * xv[cc].z + wv.w * xv[cc].w;
            }
        }
#pragma unroll
        for (int rr = 0; rr < 4; rr++) {
            int r = r0 + rr;
            float b = B2s[r];
            float s = (acc[rr][0] + b) * Wts[c0] + (acc[rr][1] + b) * Wts[c0 + 1] +
                      (acc[rr][2] + b) * Wts[c0 + 2] + (acc[rr][3] + b) * Wts[c0 + 3];
            float o = s + __shfl_down_sync(0xffffffffu, s, 1);
            if (!(t & 1)) g_sf_t[(p0 + (c0 >> 3)) * 128 + r] = o * 0.125f;
        }
    }
}

// ---------------- Kernel E: sfp path (gather cloud_feat, 128->256->128) ----------------
// 2 points (16 cols) per block, 256 threads; weights staged in k-chunks.
__global__ __launch_bounds__(256) void sfp_kernel(const float* __restrict__ w1,
                                                  const float* __restrict__ b1,
                                                  const float* __restrict__ w2,
                                                  const float* __restrict__ b2) {
    __shared__ float Xs[16][132];   // [col][k=128], padded
    __shared__ float Hs[16][260];   // [col][k=256], padded
    __shared__ float Wc[4096];      // 16 KB weight chunk
    __shared__ float Wts[16];
    int t = threadIdx.x;
    int p0 = blockIdx.x * 2;

    for (int e = t; e < 16 * 32; e += 256) {  // 512 float4 gathers
        int col = e >> 5, f = e & 31;
        int p = p0 + (col >> 3);
        int nb = g_inds_tc[p * NP + (col & 7)];
        *(float4*)&Xs[col][f * 4] = *(const float4*)&g_cf_t[nb * 128 + f * 4];
    }
    if (t < 16) Wts[t] = g_w[NCOL + p0 * NP + t];
    __syncthreads();

    {   // phase 2: H(256x16) = lrelu(W1(256x128) X + b1); tile 4x4
        int r0 = (t >> 2) * 4, c0 = (t & 3) * 4;
        float acc[4][4] = {};
        for (int kc = 0; kc < 128; kc += 16) {
            __syncthreads();
            for (int e = t; e < 1024; e += 256) {  // Wc[256][16]
                int r = e >> 2, f = e & 3;
                *(float4*)&Wc[r * 16 + f * 4] = __ldg((const float4*)(w1 + r * 128 + kc + f * 4));
            }
            __syncthreads();
#pragma unroll
            for (int k = 0; k < 16; k += 4) {
                float4 xv[4];
#pragma unroll
                for (int cc = 0; cc < 4; cc++) xv[cc] = *(float4*)&Xs[c0 + cc][kc + k];
#pragma unroll
                for (int rr = 0; rr < 4; rr++) {
                    float4 wv = *(float4*)&Wc[(r0 + rr) * 16 + k];
#pragma unroll
                    for (int cc = 0; cc < 4; cc++)
                        acc[rr][cc] += wv.x * xv[cc].x + wv.y * xv[cc].y + wv.z * xv[cc].z + wv.w * xv[cc].w;
                }
            }
        }
#pragma unroll
        for (int rr = 0; rr < 4; rr++) {
            float b = __ldg(b1 + r0 + rr);
#pragma unroll
            for (int cc = 0; cc < 4; cc++)
                Hs[c0 + cc][r0 + rr] = lrelu(acc[rr][cc] + b);
        }
    }
    __syncthreads();

    {   // phase 3: Y(128x16) = W2(128x256) H; scale; mean over 8 cols; tile 2x4
        int r0 = (t >> 2) * 2, c0 = (t & 3) * 4;
        float acc[2][4] = {};
        for (int kc = 0; kc < 256; kc += 32) {
            __syncthreads();
            for (int e = t; e < 1024; e += 256) {  // Wc[128][32]
                int r = e >> 3, f = e & 7;
                *(float4*)&Wc[r * 32 + f * 4] = __ldg((const float4*)(w2 + r * 256 + kc + f * 4));
            }
            __syncthreads();
#pragma unroll
            for (int k = 0; k < 32; k += 4) {
                float4 xv[4];
#pragma unroll
                for (int cc = 0; cc < 4; cc++) xv[cc] = *(float4*)&Hs[c0 + cc][kc + k];
#pragma unroll
                for (int rr = 0; rr < 2; rr++) {
                    float4 wv = *(float4*)&Wc[(r0 + rr) * 32 + k];
#pragma unroll
                    for (int cc = 0; cc < 4; cc++)
                        acc[rr][cc] += wv.x * xv[cc].x + wv.y * xv[cc].y + wv.z * xv[cc].z + wv.w * xv[cc].w;
                }
            }
        }
#pragma unroll
        for (int rr = 0; rr < 2; rr++) {
            int r = r0 + rr;
            float b = __ldg(b2 + r);
            float s = (acc[rr][0] + b) * Wts[c0] + (acc[rr][1] + b) * Wts[c0 + 1] +
                      (acc[rr][2] + b) * Wts[c0 + 2] + (acc[rr][3] + b) * Wts[c0 + 3];
            float o = s + __shfl_down_sync(0xffffffffu, s, 1);
            if (!(t & 1)) g_sfp_t[(p0 + (c0 >> 3)) * 128 + r] = o * 0.125f;
        }
    }
}

// ---------------- Kernel F: final FC stack ----------------
// 4 points per block, 64 threads per point (one output channel each).
__global__ __launch_bounds__(256) void final_kernel(const float* __restrict__ wfc1,
                                                    const float* __restrict__ bfc1,
                                                    const float* __restrict__ wfc2,
                                                    const float* __restrict__ bfc2,
                                                    const float* __restrict__ wfc,
                                                    const float* __restrict__ bfc,
                                                    float* __restrict__ out) {
    int t = threadIdx.x;
    int lp = t >> 6;
    int ch = t & 63;
    int p = blockIdx.x * 4 + lp;
    __shared__ float Z[4][128];

    const float* sf  = &g_sf_t[p * 128];
    const float* cf  = &g_cf_t[p * 128];
    const float* sfp = &g_sfp_t[p * 128];
    const float* im  = &g_imf_t[p * 32];

    // f1 = W_fc1 @ [sf; cloud_feat] + b
    float s1 = bfc1[ch];
    const float* w1r = wfc1 + ch * 256;
#pragma unroll 8
    for (int k = 0; k < 128; k += 4) {
        float4 w4 = __ldg((const float4*)(w1r + k));
        float4 x4 = *(const float4*)(sf + k);
        s1 += w4.x * x4.x + w4.y * x4.y + w4.z * x4.z + w4.w * x4.w;
    }
#pragma unroll 8
    for (int k = 0; k < 128; k += 4) {
        float4 w4 = __ldg((const float4*)(w1r + 128 + k));
        float4 x4 = *(const float4*)(cf + k);
        s1 += w4.x * x4.x + w4.y * x4.y + w4.z * x4.z + w4.w * x4.w;
    }
    // f2 = W_fc2 @ [sfp; imf] + b
    float s2 = bfc2[ch];
    const float* w2r = wfc2 + ch * 160;
#pragma unroll 8
    for (int k = 0; k < 128; k += 4) {
        float4 w4 = __ldg((const float4*)(w2r + k));
        float4 x4 = *(const float4*)(sfp + k);
        s2 += w4.x * x4.x + w4.y * x4.y + w4.z * x4.z + w4.w * x4.w;
    }
#pragma unroll
    for (int k = 0; k < 32; k += 4) {
        float4 w4 = __ldg((const float4*)(w2r + 128 + k));
        float4 x4 = *(const float4*)(im + k);
        s2 += w4.x * x4.x + w4.y * x4.y + w4.z * x4.z + w4.w * x4.w;
    }
    Z[lp][ch]      = lrelu(s2);   // concat([f2, f1]) order
    Z[lp][64 + ch] = lrelu(s1);
    __syncthreads();

    float o = bfc[ch];
    const float* wr = wfc + ch * 128;
#pragma unroll 8
    for (int k = 0; k < 128; k += 4) {
        float4 w4 = __ldg((const float4*)(wr + k));
        o += w4.x * Z[lp][k] + w4.y * Z[lp][k + 1] + w4.z * Z[lp][k + 2] + w4.w * Z[lp][k + 3];
    }
    out[ch * NPTS + p] = o;
}

// ---------------- launch ----------------
extern "C" void kernel_launch(void* const* d_in, const int* in_sizes, int n_in,
                              void* d_out, int out_size) {
    const float* imf   = (const float*)d_in[0];
    const float* cloud = (const float*)d_in[1];
    const float* ctar  = (const float*)d_in[2];
    const float* w_conv1   = (const float*)d_in[3];
    const float* b_conv1   = (const float*)d_in[4];
    const float* w_conv2   = (const float*)d_in[5];
    const float* b_conv2   = (const float*)d_in[6];
    const float* w_psconv1 = (const float*)d_in[7];
    const float* b_psconv1 = (const float*)d_in[8];
    const float* w_psconv2 = (const float*)d_in[9];
    const float* b_psconv2 = (const float*)d_in[10];
    const float* w_pconv1  = (const float*)d_in[11];
    const float* b_pconv1  = (const float*)d_in[12];
    const float* w_pconv2  = (const float*)d_in[13];
    const float* b_pconv2  = (const float*)d_in[14];
    const float* w_fc1 = (const float*)d_in[15];
    const float* b_fc1 = (const float*)d_in[16];
    const float* w_fc2 = (const float*)d_in[17];
    const float* b_fc2 = (const float*)d_in[18];
    const float* w_fc  = (const float*)d_in[19];
    const float* b_fc  = (const float*)d_in[20];
    float* out = (float*)d_out;

    knn_kernel<<<125, 256>>>(cloud, ctar);                       // 1000 warps
    cf_kernel<<<129, 128>>>(cloud, imf, w_pconv1, b_pconv1, w_pconv2, b_pconv2);
    softmax_kernel<<<2, 256>>>();
    sf_kernel<<<125, 256>>>(w_conv1, b_conv1, w_conv2, b_conv2);
    sfp_kernel<<<250, 256>>>(w_psconv1, b_psconv1, w_psconv2, b_psconv2);
    final_kernel<<<125, 256>>>(w_fc1, b_fc1, w_fc2, b_fc2, w_fc, b_fc, out);
}

// round 2
// speedup vs baseline: 2.0310x; 2.0310x over previous
#include <cuda_runtime.h>
#include <float.h>

#define NPTS 500
#define NP 8
#define NCOL 4000   // NPTS*NP

// ---------------- scratch (device globals) ----------------
__device__ int   g_inds[NCOL];        // knn(query=c, ref=ct) -> indices into ct
__device__ int   g_inds_tc[NCOL];     // knn(query=ct, ref=c) -> indices into c
__device__ float g_logit[2 * NCOL];   // [0:4000) dir0, [4000:8000) dir1
__device__ float g_w[2 * NCOL];       // softmax weights
__device__ float g_cf[NPTS * 128];    // cloud_feat, point-major
__device__ float g_imf[NPTS * 32];    // img_feat transposed, point-major
__device__ float g_h1[NPTS * 64];     // lrelu(W_conv1 @ imf + b), point-major
__device__ float g_hp[NPTS * 256];    // lrelu(W_psconv1 @ cloud_feat + b), point-major

__device__ __forceinline__ float lrelu(float x) { return x > 0.f ? x : 0.01f * x; }

// =======================================================================
// Kernel 1: blocks 0..124 = dual KNN (warp/query); 125..249 = cf + H1 + imf^T
// =======================================================================
__global__ __launch_bounds__(256) void k1(const float* __restrict__ c,
                                          const float* __restrict__ ct,
                                          const float* __restrict__ imf,
                                          const float* __restrict__ wp1, const float* __restrict__ bp1,
                                          const float* __restrict__ wp2, const float* __restrict__ bp2,
                                          const float* __restrict__ wc1, const float* __restrict__ bc1) {
    int t = threadIdx.x;
    if (blockIdx.x < 125) {
        // ---------------- KNN ----------------
        int gwarp = blockIdx.x * 8 + (t >> 5);     // 0..999
        int lane  = t & 31;
        int dir = gwarp >= NPTS;
        int q   = dir ? gwarp - NPTS : gwarp;
        const float* Q = dir ? ct : c;
        const float* R = dir ? c  : ct;

        float qx = Q[q * 3 + 0], qy = Q[q * 3 + 1], qz = Q[q * 3 + 2];
        float qq = qx * qx + qy * qy + qz * qz;

        float bd[8]; int bi[8];
#pragma unroll
        for (int k = 0; k < 8; k++) { bd[k] = FLT_MAX; bi[k] = 0x3fffffff; }

        for (int j = lane; j < NPTS; j += 32) {
            float rx = R[j * 3 + 0], ry = R[j * 3 + 1], rz = R[j * 3 + 2];
            float d2 = qq - 2.f * (qx * rx + qy * ry + qz * rz) + (rx * rx + ry * ry + rz * rz);
            if (d2 < bd[7] || (d2 == bd[7] && j < bi[7])) {
                bd[7] = d2; bi[7] = j;
#pragma unroll
                for (int k = 7; k > 0; k--) {
                    if (bd[k] < bd[k - 1] || (bd[k] == bd[k - 1] && bi[k] < bi[k - 1])) {
                        float td = bd[k]; bd[k] = bd[k - 1]; bd[k - 1] = td;
                        int   ti = bi[k]; bi[k] = bi[k - 1]; bi[k - 1] = ti;
                    }
                }
            }
        }

        int*   outi = dir ? g_inds_tc : g_inds;
        float* outl = dir ? (g_logit + NCOL) : g_logit;

#pragma unroll
        for (int s = 0; s < NP; s++) {
            float md = bd[0]; int mi = bi[0];
#pragma unroll
            for (int off = 16; off; off >>= 1) {
                float od = __shfl_xor_sync(0xffffffffu, md, off);
                int   oi = __shfl_xor_sync(0xffffffffu, mi, off);
                if (od < md || (od == md && oi < mi)) { md = od; mi = oi; }
            }
            if (lane == 0) {
                outi[q * NP + s] = mi;
                float dx = qx - R[mi * 3 + 0];
                float dy = qy - R[mi * 3 + 1];
                float dz = qz - R[mi * 3 + 2];
                outl[q * NP + s] = -sqrtf(dx * dx + dy * dy + dz * dz);
            }
            if (bi[0] == mi) {
#pragma unroll
                for (int k = 0; k < 7; k++) { bd[k] = bd[k + 1]; bi[k] = bi[k + 1]; }
                bd[7] = FLT_MAX; bi[7] = 0x3fffffff;
            }
        }
        return;
    }

    // ---------------- cf (3->64->128) + H1 (32->64) + imf transpose, 4 pts ----------------
    __shared__ float Hs[4][64];
    __shared__ float Is[4][32];
    int p0 = (blockIdx.x - 125) * 4;

    if (t < 128) {                       // stage imf cols + transpose out
        int lp = t >> 5, ch = t & 31;
        float v = imf[ch * NPTS + (p0 + lp)];
        Is[lp][ch] = v;
        g_imf[(p0 + lp) * 32 + ch] = v;
    }
    {                                    // H64 = lrelu(Wp1 @ c + b)
        int lp = t >> 6, r = t & 63;
        int p = p0 + lp;
        float h = bp1[r] + wp1[r * 3 + 0] * c[p * 3 + 0] + wp1[r * 3 + 1] * c[p * 3 + 1]
                         + wp1[r * 3 + 2] * c[p * 3 + 2];
        Hs[lp][r] = lrelu(h);
    }
    __syncthreads();
    {                                    // cf = Wp2(128x64) @ H64 + b  (2 cols/thread)
        int r = t & 127, half = t >> 7;
        float acc[2] = {};
        const float* wr = wp2 + r * 64;
#pragma unroll
        for (int k = 0; k < 64; k += 4) {
            float4 w4 = __ldg((const float4*)(wr + k));
#pragma unroll
            for (int cc = 0; cc < 2; cc++) {
                float4 x4 = *(float4*)&Hs[half * 2 + cc][k];
                acc[cc] += w4.x * x4.x + w4.y * x4.y + w4.z * x4.z + w4.w * x4.w;
            }
        }
        float b = __ldg(bp2 + r);
#pragma unroll
        for (int cc = 0; cc < 2; cc++)
            g_cf[(p0 + half * 2 + cc) * 128 + r] = acc[cc] + b;
    }
    {                                    // H1 = lrelu(Wc1(64x32) @ imf + b)
        int lp = t >> 6, r = t & 63;
        float acc = __ldg(bc1 + r);
        const float* wr = wc1 + r * 32;
#pragma unroll
        for (int k = 0; k < 32; k += 4) {
            float4 w4 = __ldg((const float4*)(wr + k));
            float4 x4 = *(float4*)&Is[lp][k];
            acc += w4.x * x4.x + w4.y * x4.y + w4.z * x4.z + w4.w * x4.w;
        }
        g_h1[(p0 + lp) * 64 + r] = lrelu(acc);
    }
}

// =======================================================================
// Kernel 2: blocks 0,1 = global softmax; 2..126 = Hp = lrelu(Wps1 @ cf + b)
// =======================================================================
__global__ __launch_bounds__(256) void k2(const float* __restrict__ wps1,
                                          const float* __restrict__ bps1) {
    int t = threadIdx.x;
    if (blockIdx.x < 2) {
        int d = blockIdx.x;
        const float* x = g_logit + d * NCOL;
        float*       y = g_w + d * NCOL;
        __shared__ float red[256];
        float m = -FLT_MAX;
        for (int i = t; i < NCOL; i += 256) m = fmaxf(m, x[i]);
        red[t] = m; __syncthreads();
        for (int s = 128; s; s >>= 1) { if (t < s) red[t] = fmaxf(red[t], red[t + s]); __syncthreads(); }
        m = red[0]; __syncthreads();
        float sum = 0.f;
        for (int i = t; i < NCOL; i += 256) sum += expf(x[i] - m);
        red[t] = sum; __syncthreads();
        for (int s = 128; s; s >>= 1) { if (t < s) red[t] += red[t + s]; __syncthreads(); }
        float inv = 1.f / red[0];
        for (int i = t; i < NCOL; i += 256) y[i] = expf(x[i] - m) * inv;
        return;
    }

    // Hp: 256 rows x 4 cols, K=128.  thread = row, 4 cols each.
    __shared__ float Xs[4][128];
    int p0 = (blockIdx.x - 2) * 4;
    if (t < 128) {
        int col = t >> 5, f = t & 31;
        *(float4*)&Xs[col][f * 4] = *(const float4*)&g_cf[(p0 + col) * 128 + f * 4];
    }
    __syncthreads();

    int r = t;
    float acc[4] = {};
    const float* wr = wps1 + r * 128;
#pragma unroll 8
    for (int k = 0; k < 128; k += 4) {
        float4 w4 = __ldg((const float4*)(wr + k));
#pragma unroll
        for (int cc = 0; cc < 4; cc++) {
            float4 x4 = *(float4*)&Xs[cc][k];
            acc[cc] += w4.x * x4.x + w4.y * x4.y + w4.z * x4.z + w4.w * x4.w;
        }
    }
    float b = __ldg(bps1 + r);
#pragma unroll
    for (int cc = 0; cc < 4; cc++)
        g_hp[(p0 + cc) * 256 + r] = lrelu(acc[cc] + b);
}

// =======================================================================
// Kernel 3: per block = 4 points: weighted gathers -> Y1, Y2 -> final FC -> out
// =======================================================================
__global__ __launch_bounds__(256) void k3(const float* __restrict__ wc2,  const float* __restrict__ bc2,
                                          const float* __restrict__ wps2, const float* __restrict__ bps2,
                                          const float* __restrict__ wfc1, const float* __restrict__ bfc1,
                                          const float* __restrict__ wfc2, const float* __restrict__ bfc2,
                                          const float* __restrict__ wfc,  const float* __restrict__ bfc,
                                          float* __restrict__ out) {
    __shared__ float Wt0[32], Wt1[32], Ws0[4], Ws1[4];
    __shared__ int   I0[32], I1[32];
    __shared__ float Hb[4][68];     // weighted-mean H1 (64), padded
    __shared__ float Hpb[4][260];   // weighted-mean Hp (256), padded
    __shared__ float Sf[4][128];
    __shared__ float Sfp[4][128];
    __shared__ float Cf[4][128];
    __shared__ float Im[4][32];
    __shared__ float Z[4][128];

    int t = threadIdx.x;
    int p0 = blockIdx.x * 4;

    if (t < 32) {
        int e = p0 * NP + t;
        I0[t]  = g_inds[e];     Wt0[t] = g_w[e];
        I1[t]  = g_inds_tc[e];  Wt1[t] = g_w[NCOL + e];
    }
    if (t < 128) {                      // stage cf
        int col = t >> 5, f = t & 31;
        *(float4*)&Cf[col][f * 4] = *(const float4*)&g_cf[(p0 + col) * 128 + f * 4];
    }
    if (t < 32) {                       // stage imf
        int col = t >> 3, f = t & 7;
        *(float4*)&Im[col][f * 4] = *(const float4*)&g_imf[(p0 + col) * 32 + f * 4];
    }
    __syncthreads();

    if (t < 4) {                        // mean softmax weight per point (dir0)
        float s = 0;
#pragma unroll
        for (int j = 0; j < 8; j++) s += Wt0[t * 8 + j];
        Ws0[t] = 0.125f * s;
    } else if (t < 8) {
        int lp = t - 4;
        float s = 0;
#pragma unroll
        for (int j = 0; j < 8; j++) s += Wt1[lp * 8 + j];
        Ws1[lp] = 0.125f * s;
    }
    {                                   // Hbar = mean_j w_j * H1[:, idx_j]   (4x64)
        int lp = t >> 6, r = t & 63;
        float s = 0;
#pragma unroll
        for (int j = 0; j < 8; j++)
            s += Wt0[lp * 8 + j] * g_h1[I0[lp * 8 + j] * 64 + r];
        Hb[lp][r] = 0.125f * s;
    }
    {                                   // Hpbar (4x256)
        int r = t;
#pragma unroll
        for (int lp = 0; lp < 4; lp++) {
            float s = 0;
#pragma unroll
            for (int j = 0; j < 8; j++)
                s += Wt1[lp * 8 + j] * g_hp[I1[lp * 8 + j] * 256 + r];
            Hpb[lp][r] = 0.125f * s;
        }
    }
    __syncthreads();

    {                                   // Y1 = Wc2(128x64) @ Hbar + bc2 * ws0   (2 cols/thread)
        int r = t & 127, half = t >> 7;
        float acc[2] = {};
        const float* wr = wc2 + r * 64;
#pragma unroll
        for (int k = 0; k < 64; k += 4) {
            float4 w4 = __ldg((const float4*)(wr + k));
#pragma unroll
            for (int cc = 0; cc < 2; cc++) {
                float4 x4 = *(float4*)&Hb[half * 2 + cc][k];
                acc[cc] += w4.x * x4.x + w4.y * x4.y + w4.z * x4.z + w4.w * x4.w;
            }
        }
        float b = __ldg(bc2 + r);
#pragma unroll
        for (int cc = 0; cc < 2; cc++)
            Sf[half * 2 + cc][r] = acc[cc] + b * Ws0[half * 2 + cc];
    }
    {                                   // Y2 = Wps2(128x256) @ Hpbar + bps2 * ws1
        int r = t & 127, half = t >> 7;
        float acc[2] = {};
        const float* wr = wps2 + r * 256;
#pragma unroll 8
        for (int k = 0; k < 256; k += 4) {
            float4 w4 = __ldg((const float4*)(wr + k));
#pragma unroll
            for (int cc = 0; cc < 2; cc++) {
                float4 x4 = *(float4*)&Hpb[half * 2 + cc][k];
                acc[cc] += w4.x * x4.x + w4.y * x4.y + w4.z * x4.z + w4.w * x4.w;
            }
        }
        float b = __ldg(bps2 + r);
#pragma unroll
        for (int cc = 0; cc < 2; cc++)
            Sfp[half * 2 + cc][r] = acc[cc] + b * Ws1[half * 2 + cc];
    }
    __syncthreads();

    // final FC stack: thread = (point lp, channel ch)
    int ch = t & 63, lp = t >> 6;
    {
        float f1 = __ldg(bfc1 + ch);
        const float* w1r = wfc1 + ch * 256;
#pragma unroll 8
        for (int k = 0; k < 128; k += 4) {
            float4 w4 = __ldg((const float4*)(w1r + k));
            float4 x4 = *(float4*)&Sf[lp][k];
            f1 += w4.x * x4.x + w4.y * x4.y + w4.z * x4.z + w4.w * x4.w;
        }
#pragma unroll 8
        for (int k = 0; k < 128; k += 4) {
            float4 w4 = __ldg((const float4*)(w1r + 128 + k));
            float4 x4 = *(float4*)&Cf[lp][k];
            f1 += w4.x * x4.x + w4.y * x4.y + w4.z * x4.z + w4.w * x4.w;
        }
        float f2 = __ldg(bfc2 + ch);
        const float* w2r = wfc2 + ch * 160;
#pragma unroll 8
        for (int k = 0; k < 128; k += 4) {
            float4 w4 = __ldg((const float4*)(w2r + k));
            float4 x4 = *(float4*)&Sfp[lp][k];
            f2 += w4.x * x4.x + w4.y * x4.y + w4.z * x4.z + w4.w * x4.w;
        }
#pragma unroll
        for (int k = 0; k < 32; k += 4) {
            float4 w4 = __ldg((const float4*)(w2r + 128 + k));
            float4 x4 = *(float4*)&Im[lp][k];
            f2 += w4.x * x4.x + w4.y * x4.y + w4.z * x4.z + w4.w * x4.w;
        }
        Z[lp][ch]      = lrelu(f2);      // concat([f2, f1])
        Z[lp][64 + ch] = lrelu(f1);
    }
    __syncthreads();
    {
        float o = __ldg(bfc + ch);
        const float* wr = wfc + ch * 128;
#pragma unroll 8
        for (int k = 0; k < 128; k += 4) {
            float4 w4 = __ldg((const float4*)(wr + k));
            float4 z4 = *(float4*)&Z[lp][k];
            o += w4.x * z4.x + w4.y * z4.y + w4.z * z4.z + w4.w * z4.w;
        }
        out[ch * NPTS + (p0 + lp)] = o;
    }
}

// ---------------- launch ----------------
extern "C" void kernel_launch(void* const* d_in, const int* in_sizes, int n_in,
                              void* d_out, int out_size) {
    const float* imf   = (const float*)d_in[0];
    const float* cloud = (const float*)d_in[1];
    const float* ctar  = (const float*)d_in[2];
    const float* w_conv1   = (const float*)d_in[3];
    const float* b_conv1   = (const float*)d_in[4];
    const float* w_conv2   = (const float*)d_in[5];
    const float* b_conv2   = (const float*)d_in[6];
    const float* w_psconv1 = (const float*)d_in[7];
    const float* b_psconv1 = (const float*)d_in[8];
    const float* w_psconv2 = (const float*)d_in[9];
    const float* b_psconv2 = (const float*)d_in[10];
    const float* w_pconv1  = (const float*)d_in[11];
    const float* b_pconv1  = (const float*)d_in[12];
    const float* w_pconv2  = (const float*)d_in[13];
    const float* b_pconv2  = (const float*)d_in[14];
    const float* w_fc1 = (const float*)d_in[15];
    const float* b_fc1 = (const float*)d_in[16];
    const float* w_fc2 = (const float*)d_in[17];
    const float* b_fc2 = (const float*)d_in[18];
    const float* w_fc  = (const float*)d_in[19];
    const float* b_fc  = (const float*)d_in[20];
    float* out = (float*)d_out;

    k1<<<250, 256>>>(cloud, ctar, imf, w_pconv1, b_pconv1, w_pconv2, b_pconv2, w_conv1, b_conv1);
    k2<<<127, 256>>>(w_psconv1, b_psconv1);
    k3<<<125, 256>>>(w_conv2, b_conv2, w_psconv2, b_psconv2,
                     w_fc1, b_fc1, w_fc2, b_fc2, w_fc, b_fc, out);
}

// round 4
// speedup vs baseline: 3.1234x; 1.5379x over previous
#include <cuda_runtime.h>
#include <float.h>

#define NPTS 500
#define NP 8
#define NCOL 4000   // NPTS*NP

// ---------------- scratch (device globals) ----------------
__device__ int   g_inds[NCOL];        // knn(query=c, ref=ct)
__device__ int   g_inds_tc[NCOL];     // knn(query=ct, ref=c)
__device__ float g_expw[2 * NCOL];    // exp(-dist) raw (softmax numerators)
__device__ float g_cf[NPTS * 128];    // cloud_feat, point-major
__device__ float g_imf[NPTS * 32];    // img_feat transposed, point-major
__device__ float g_h1[NPTS * 64];     // lrelu(Wc1 @ imf + b), point-major
__device__ float g_hp[NPTS * 256];    // lrelu(Wps1 @ cf + b), point-major
// transposed weights (k-major) for coalesced reads in k3
__device__ float g_wps2T[256 * 128];
__device__ float g_wc2T [64 * 128];
__device__ float g_wfc1T[256 * 64];
__device__ float g_wfc2T[160 * 64];
__device__ float g_wfcT [128 * 64];

__device__ __forceinline__ float lrelu(float x) { return x > 0.f ? x : 0.01f * x; }
__device__ __forceinline__ unsigned ordf(float f) {
    unsigned u = __float_as_uint(f);
    return (u & 0x80000000u) ? ~u : (u | 0x80000000u);
}

// =======================================================================
// Kernel 1:
//   blocks [0,125): dual KNN, warp/query, clouds staged in smem, REDUX select
//   blocks [125,250): per-point features: imf^T, H64, cf, h1, Hp (warp-dot)
//   blocks [250,324): 32x32 tiled weight transposes
// =======================================================================
__global__ __launch_bounds__(256) void k1(const float* __restrict__ c,
                                          const float* __restrict__ ct,
                                          const float* __restrict__ imf,
                                          const float* __restrict__ wp1, const float* __restrict__ bp1,
                                          const float* __restrict__ wp2, const float* __restrict__ bp2,
                                          const float* __restrict__ wc1, const float* __restrict__ bc1,
                                          const float* __restrict__ wps1, const float* __restrict__ bps1,
                                          const float* __restrict__ wps2,
                                          const float* __restrict__ wc2,
                                          const float* __restrict__ wfc1,
                                          const float* __restrict__ wfc2,
                                          const float* __restrict__ wfc) {
    __shared__ __align__(16) float sb[3008];
    int t = threadIdx.x;

    if (blockIdx.x < 125) {
        // ---------------- KNN ----------------
        float* Pc = sb;          // c  (1500)
        float* Pt = sb + 1504;   // ct (1500)
        for (int i = t; i < 1500; i += 256) { Pc[i] = c[i]; Pt[i] = ct[i]; }
        __syncthreads();

        int warp = t >> 5, lane = t & 31;
        int gw = blockIdx.x * 8 + warp;       // 0..999
        int dir = gw >= NPTS;
        int q = dir ? gw - NPTS : gw;
        const float* Q = dir ? Pt : Pc;
        const float* R = dir ? Pc : Pt;

        float qx = Q[q * 3 + 0], qy = Q[q * 3 + 1], qz = Q[q * 3 + 2];
        float qq = qx * qx + qy * qy + qz * qz;

        float bd[8]; int bi[8];
#pragma unroll
        for (int k = 0; k < 8; k++) { bd[k] = FLT_MAX; bi[k] = 0x3fffffff; }

#pragma unroll 4
        for (int j = lane; j < NPTS; j += 32) {
            float rx = R[j * 3 + 0], ry = R[j * 3 + 1], rz = R[j * 3 + 2];
            float d2 = qq - 2.f * (qx * rx + qy * ry + qz * rz) + (rx * rx + ry * ry + rz * rz);
            if (d2 < bd[7] || (d2 == bd[7] && j < bi[7])) {
                bd[7] = d2; bi[7] = j;
#pragma unroll
                for (int k = 7; k > 0; k--) {
                    if (bd[k] < bd[k - 1] || (bd[k] == bd[k - 1] && bi[k] < bi[k - 1])) {
                        float td = bd[k]; bd[k] = bd[k - 1]; bd[k - 1] = td;
                        int   ti = bi[k]; bi[k] = bi[k - 1]; bi[k - 1] = ti;
                    }
                }
            }
        }

        int*   outi = dir ? g_inds_tc : g_inds;
        float* oute = dir ? (g_expw + NCOL) : g_expw;

#pragma unroll
        for (int s = 0; s < NP; s++) {
            unsigned key = ordf(bd[0]);
            unsigned mk  = __reduce_min_sync(0xffffffffu, key);
            unsigned cand = (key == mk) ? (unsigned)bi[0] : 0xffffffffu;
            unsigned sel  = __reduce_min_sync(0xffffffffu, cand);
            if (lane == 0) {
                outi[q * NP + s] = (int)sel;
                float dx = qx - R[sel * 3 + 0];
                float dy = qy - R[sel * 3 + 1];
                float dz = qz - R[sel * 3 + 2];
                oute[q * NP + s] = expf(-sqrtf(dx * dx + dy * dy + dz * dz));
            }
            if (key == mk && (unsigned)bi[0] == sel) {   // pop on owning lane
#pragma unroll
                for (int k = 0; k < 7; k++) { bd[k] = bd[k + 1]; bi[k] = bi[k + 1]; }
                bd[7] = FLT_MAX; bi[7] = 0x3fffffff;
            }
        }
        return;
    }

    if (blockIdx.x < 250) {
        // ---------------- feature block: 4 points ----------------
        float (*Hs)[64]   = (float(*)[64])sb;          // 256 floats
        float (*Is)[32]   = (float(*)[32])(sb + 256);  // 128 floats
        float (*CFs)[128] = (float(*)[128])(sb + 384); // 512 floats (sb+384: 1536B, 16-aligned)
        int p0 = (blockIdx.x - 125) * 4;
        int warp = t >> 5, lane = t & 31;

        if (t < 128) {                       // stage imf cols + transpose out
            int lp = t >> 5, chn = t & 31;
            float v = imf[chn * NPTS + (p0 + lp)];
            Is[lp][chn] = v;
            g_imf[(p0 + lp) * 32 + chn] = v;
        }
        {                                    // H64 = lrelu(Wp1 @ c + b)
            int lp = t >> 6, r = t & 63;
            int p = p0 + lp;
            float h = bp1[r] + wp1[r * 3 + 0] * c[p * 3 + 0] + wp1[r * 3 + 1] * c[p * 3 + 1]
                             + wp1[r * 3 + 2] * c[p * 3 + 2];
            Hs[lp][r] = lrelu(h);
        }
        __syncthreads();

        {   // cf = Wp2(128x64) @ H64 + b  -- warp-dot: 8 warps x 16 rows, lane = 2 K
            float2 hx[4];
#pragma unroll
            for (int cc = 0; cc < 4; cc++) hx[cc] = *(float2*)&Hs[cc][lane * 2];
#pragma unroll 2
            for (int i = 0; i < 16; i++) {
                int r = warp * 16 + i;
                float2 w2 = __ldg((const float2*)(wp2 + r * 64 + lane * 2));
                float p[4];
#pragma unroll
                for (int cc = 0; cc < 4; cc++) p[cc] = w2.x * hx[cc].x + w2.y * hx[cc].y;
#pragma unroll
                for (int off = 16; off; off >>= 1)
#pragma unroll
                    for (int cc = 0; cc < 4; cc++) p[cc] += __shfl_xor_sync(0xffffffffu, p[cc], off);
                if (lane == 0) {
                    float bb = __ldg(bp2 + r);
#pragma unroll
                    for (int cc = 0; cc < 4; cc++) {
                        float v = p[cc] + bb;
                        g_cf[(p0 + cc) * 128 + r] = v;
                        CFs[cc][r] = v;
                    }
                }
            }
        }
        {   // h1 = lrelu(Wc1(64x32) @ imf + b) -- warp-dot: 8 warps x 8 rows, lane = 1 K
            float xi[4];
#pragma unroll
            for (int cc = 0; cc < 4; cc++) xi[cc] = Is[cc][lane];
#pragma unroll
            for (int i = 0; i < 8; i++) {
                int r = warp * 8 + i;
                float w = __ldg(wc1 + r * 32 + lane);
                float p[4];
#pragma unroll
                for (int cc = 0; cc < 4; cc++) p[cc] = w * xi[cc];
#pragma unroll
                for (int off = 16; off; off >>= 1)
#pragma unroll
                    for (int cc = 0; cc < 4; cc++) p[cc] += __shfl_xor_sync(0xffffffffu, p[cc], off);
                if (lane == 0) {
                    float bb = __ldg(bc1 + r);
#pragma unroll
                    for (int cc = 0; cc < 4; cc++)
                        g_h1[(p0 + cc) * 64 + r] = lrelu(p[cc] + bb);
                }
            }
        }
        __syncthreads();
        {   // Hp = lrelu(Wps1(256x128) @ cf + b) -- warp-dot: 8 warps x 32 rows, lane = 4 K
            float4 xv[4];
#pragma unroll
            for (int cc = 0; cc < 4; cc++) xv[cc] = *(float4*)&CFs[cc][lane * 4];
#pragma unroll 2
            for (int i = 0; i < 32; i++) {
                int r = warp * 32 + i;
                float4 wv = __ldg((const float4*)(wps1 + r * 128 + lane * 4));
                float p[4];
#pragma unroll
                for (int cc = 0; cc < 4; cc++)
                    p[cc] = wv.x * xv[cc].x + wv.y * xv[cc].y + wv.z * xv[cc].z + wv.w * xv[cc].w;
#pragma unroll
                for (int off = 16; off; off >>= 1)
#pragma unroll
                    for (int cc = 0; cc < 4; cc++) p[cc] += __shfl_xor_sync(0xffffffffu, p[cc], off);
                if (lane == 0) {
                    float bb = __ldg(bps1 + r);
#pragma unroll
                    for (int cc = 0; cc < 4; cc++)
                        g_hp[(p0 + cc) * 256 + r] = lrelu(p[cc] + bb);
                }
            }
        }
        return;
    }

    // ---------------- transpose blocks: one 32x32 tile each ----------------
    {
        int bb = blockIdx.x - 250;
        const float* src; float* dst; int R, C, tile;
        if      (bb < 32) { src = wps2; dst = g_wps2T; R = 128; C = 256; tile = bb; }
        else if (bb < 40) { src = wc2;  dst = g_wc2T;  R = 128; C = 64;  tile = bb - 32; }
        else if (bb < 56) { src = wfc1; dst = g_wfc1T; R = 64;  C = 256; tile = bb - 40; }
        else if (bb < 66) { src = wfc2; dst = g_wfc2T; R = 64;  C = 160; tile = bb - 56; }
        else              { src = wfc;  dst = g_wfcT;  R = 64;  C = 128; tile = bb - 66; }
        int tilesC = C / 32;
        int tr = (tile / tilesC) * 32, tc = (tile % tilesC) * 32;
        float (*S)[33] = (float(*)[33])sb;
        int r = t >> 3, q = t & 7;
        float4 v = *(const float4*)(src + (tr + r) * C + tc + q * 4);
        S[r][q * 4 + 0] = v.x; S[r][q * 4 + 1] = v.y; S[r][q * 4 + 2] = v.z; S[r][q * 4 + 3] = v.w;
        __syncthreads();
        float4 o;
        o.x = S[q * 4 + 0][r]; o.y = S[q * 4 + 1][r]; o.z = S[q * 4 + 2][r]; o.w = S[q * 4 + 3][r];
        *(float4*)(dst + (tc + r) * R + tr + q * 4) = o;
    }
}

// =======================================================================
// Kernel 2 (k3): 125 blocks x 4 points: S-reduce, gathers, Y1/Y2, final FC
// =======================================================================
__global__ __launch_bounds__(256) void k3(const float* __restrict__ bc2,
                                          const float* __restrict__ bps2,
                                          const float* __restrict__ bfc1,
                                          const float* __restrict__ bfc2,
                                          const float* __restrict__ bfc,
                                          float* __restrict__ out) {
    __shared__ __align__(16) float red0[256];
    __shared__ __align__(16) float red1[256];
    __shared__ __align__(16) float invS[4];
    __shared__ __align__(16) int   I0[32];
    __shared__ __align__(16) int   I1[32];
    __shared__ __align__(16) float W0[32];
    __shared__ __align__(16) float W1[32];
    __shared__ __align__(16) float Ws0[4];
    __shared__ __align__(16) float Ws1[4];
    __shared__ __align__(16) float Hb[4][64];
    __shared__ __align__(16) float Hpb[4][256];
    __shared__ __align__(16) float A1[4][256];   // [0:128)=Sf  [128:256)=Cf
    __shared__ __align__(16) float A2[4][160];   // [0:128)=Sfp [128:160)=Im
    __shared__ __align__(16) float Z[4][128];
    __shared__ __align__(16) float P[4096];      // partial buffer (16KB)

    int t = threadIdx.x;
    int p0 = blockIdx.x * 4;

    // stage block data (pre-sync)
    if (t < 32) {
        int e = p0 * NP + t;
        I0[t] = g_inds[e];    W0[t] = g_expw[e];
        I1[t] = g_inds_tc[e]; W1[t] = g_expw[NCOL + e];
    }
    if (t < 128) {                       // Cf -> A1 upper half
        int col = t >> 5, f = t & 31;
        *(float4*)&A1[col][128 + f * 4] = *(const float4*)&g_cf[(p0 + col) * 128 + f * 4];
    } else if (t < 160) {                // Im -> A2 upper region
        int tt = t - 128;
        int col = tt >> 3, f = tt & 7;
        *(float4*)&A2[col][128 + f * 4] = *(const float4*)&g_imf[(p0 + col) * 32 + f * 4];
    }

    // global softmax denominators (all logits <= 0, exp <= 1: no max shift needed)
    float s0 = 0.f, s1 = 0.f;
    for (int i = t; i < NCOL; i += 256) { s0 += g_expw[i]; s1 += g_expw[NCOL + i]; }
    red0[t] = s0; red1[t] = s1; __syncthreads();
    for (int s = 128; s; s >>= 1) {
        if (t < s) { red0[t] += red0[t + s]; red1[t] += red1[t + s]; }
        __syncthreads();
    }
    if (t == 0) { invS[0] = 1.f / red0[0]; invS[1] = 1.f / red1[0]; }
    __syncthreads();
    float inv0 = invS[0], inv1 = invS[1];

    if (t < 4) {
        float s = 0;
#pragma unroll
        for (int j = 0; j < 8; j++) s += W0[t * 8 + j];
        Ws0[t] = 0.125f * inv0 * s;
    } else if (t < 8) {
        int lp = t - 4; float s = 0;
#pragma unroll
        for (int j = 0; j < 8; j++) s += W1[lp * 8 + j];
        Ws1[lp] = 0.125f * inv1 * s;
    }
    {                                   // Hbar (4x64)
        int lp = t >> 6, r = t & 63;
        float s = 0;
#pragma unroll
        for (int j = 0; j < 8; j++) s += W0[lp * 8 + j] * g_h1[I0[lp * 8 + j] * 64 + r];
        Hb[lp][r] = 0.125f * inv0 * s;
    }
    {                                   // Hpbar (4x256)
        int r = t;
#pragma unroll
        for (int lp = 0; lp < 4; lp++) {
            float s = 0;
#pragma unroll
            for (int j = 0; j < 8; j++) s += W1[lp * 8 + j] * g_hp[I1[lp * 8 + j] * 256 + r];
            Hpb[lp][r] = 0.125f * inv1 * s;
        }
    }
    __syncthreads();

    // ---- Y2 partials: 128 rows, K=256. rq = t&31 (rows rq*4..+3), ks = t>>5 (8 x K=32)
    {
        int rq = t & 31, ks = t >> 5;
        float4 a[4] = {};
        const float* wp = g_wps2T + (ks * 32) * 128 + rq * 4;
#pragma unroll 8
        for (int k = 0; k < 32; k++) {
            float4 w4 = *(const float4*)(wp + k * 128);
            int kk = ks * 32 + k;
#pragma unroll
            for (int cc = 0; cc < 4; cc++) {
                float x = Hpb[cc][kk];
                a[cc].x += w4.x * x; a[cc].y += w4.y * x; a[cc].z += w4.z * x; a[cc].w += w4.w * x;
            }
        }
#pragma unroll
        for (int cc = 0; cc < 4; cc++)
            *(float4*)&P[(ks * 4 + cc) * 128 + rq * 4] = a[cc];
    }
    __syncthreads();
    for (int o = t; o < 512; o += 256) {   // reduce -> Sfp (A2 low)
        int r = o & 127, cc = o >> 7;
        float s = 0;
#pragma unroll
        for (int ks = 0; ks < 8; ks++) s += P[(ks * 4 + cc) * 128 + r];
        A2[cc][r] = s + bps2[r] * Ws1[cc];
    }
    __syncthreads();

    // ---- Y1 partials: 128 rows, K=64. ks = t>>5 (8 x K=8)
    {
        int rq = t & 31, ks = t >> 5;
        float4 a[4] = {};
        const float* wp = g_wc2T + (ks * 8) * 128 + rq * 4;
#pragma unroll
        for (int k = 0; k < 8; k++) {
            float4 w4 = *(const float4*)(wp + k * 128);
            int kk = ks * 8 + k;
#pragma unroll
            for (int cc = 0; cc < 4; cc++) {
                float x = Hb[cc][kk];
                a[cc].x += w4.x * x; a[cc].y += w4.y * x; a[cc].z += w4.z * x; a[cc].w += w4.w * x;
            }
        }
#pragma unroll
        for (int cc = 0; cc < 4; cc++)
            *(float4*)&P[(ks * 4 + cc) * 128 + rq * 4] = a[cc];
    }
    __syncthreads();
    for (int o = t; o < 512; o += 256) {   // reduce -> Sf (A1 low)
        int r = o & 127, cc = o >> 7;
        float s = 0;
#pragma unroll
        for (int ks = 0; ks < 8; ks++) s += P[(ks * 4 + cc) * 128 + r];
        A1[cc][r] = s + bc2[r] * Ws0[cc];
    }
    __syncthreads();

    // ---- f1: 64 rows, K=256 over A1. rq = t&15, ks = t>>4 (16 x K=16)
    {
        int rq = t & 15, ks = t >> 4;
        float4 a[4] = {};
        const float* wp = g_wfc1T + (ks * 16) * 64 + rq * 4;
#pragma unroll 4
        for (int k = 0; k < 16; k++) {
            float4 w4 = *(const float4*)(wp + k * 64);
            int kk = ks * 16 + k;
#pragma unroll
            for (int cc = 0; cc < 4; cc++) {
                float x = A1[cc][kk];
                a[cc].x += w4.x * x; a[cc].y += w4.y * x; a[cc].z += w4.z * x; a[cc].w += w4.w * x;
            }
        }
#pragma unroll
        for (int cc = 0; cc < 4; cc++)
            *(float4*)&P[(ks * 4 + cc) * 64 + rq * 4] = a[cc];
    }
    __syncthreads();
    {                                       // reduce -> Z[:,64+ch]
        int ch = t & 63, cc = t >> 6;
        float s = 0;
#pragma unroll
        for (int ks = 0; ks < 16; ks++) s += P[(ks * 4 + cc) * 64 + ch];
        Z[cc][64 + ch] = lrelu(s + bfc1[ch]);
    }
    __syncthreads();

    // ---- f2: 64 rows, K=160 over A2. ks = t>>4 (16 x K=10)
    {
        int rq = t & 15, ks = t >> 4;
        float4 a[4] = {};
        const float* wp = g_wfc2T + (ks * 10) * 64 + rq * 4;
#pragma unroll
        for (int k = 0; k < 10; k++) {
            float4 w4 = *(const float4*)(wp + k * 64);
            int kk = ks * 10 + k;
#pragma unroll
            for (int cc = 0; cc < 4; cc++) {
                float x = A2[cc][kk];
                a[cc].x += w4.x * x; a[cc].y += w4.y * x; a[cc].z += w4.z * x; a[cc].w += w4.w * x;
            }
        }
#pragma unroll
        for (int cc = 0; cc < 4; cc++)
            *(float4*)&P[(ks * 4 + cc) * 64 + rq * 4] = a[cc];
    }
    __syncthreads();
    {                                       // reduce -> Z[:,ch]
        int ch = t & 63, cc = t >> 6;
        float s = 0;
#pragma unroll
        for (int ks = 0; ks < 16; ks++) s += P[(ks * 4 + cc) * 64 + ch];
        Z[cc][ch] = lrelu(s + bfc2[ch]);
    }
    __syncthreads();

    // ---- out: 64 rows, K=128 over Z. ks = t>>4 (16 x K=8)
    {
        int rq = t & 15, ks = t >> 4;
        float4 a[4] = {};
        const float* wp = g_wfcT + (ks * 8) * 64 + rq * 4;
#pragma unroll
        for (int k = 0; k < 8; k++) {
            float4 w4 = *(const float4*)(wp + k * 64);
            int kk = ks * 8 + k;
#pragma unroll
            for (int cc = 0; cc < 4; cc++) {
                float x = Z[cc][kk];
                a[cc].x += w4.x * x; a[cc].y += w4.y * x; a[cc].z += w4.z * x; a[cc].w += w4.w * x;
            }
        }
#pragma unroll
        for (int cc = 0; cc < 4; cc++)
            *(float4*)&P[(ks * 4 + cc) * 64 + rq * 4] = a[cc];
    }
    __syncthreads();
    {
        int ch = t & 63, cc = t >> 6;
        float s = 0;
#pragma unroll
        for (int ks = 0; ks < 16; ks++) s += P[(ks * 4 + cc) * 64 + ch];
        out[ch * NPTS + (p0 + cc)] = s + bfc[ch];
    }
}

// ---------------- launch ----------------
extern "C" void kernel_launch(void* const* d_in, const int* in_sizes, int n_in,
                              void* d_out, int out_size) {
    const float* imf   = (const float*)d_in[0];
    const float* cloud = (const float*)d_in[1];
    const float* ctar  = (const float*)d_in[2];
    const float* w_conv1   = (const float*)d_in[3];
    const float* b_conv1   = (const float*)d_in[4];
    const float* w_conv2   = (const float*)d_in[5];
    const float* b_conv2   = (const float*)d_in[6];
    const float* w_psconv1 = (const float*)d_in[7];
    const float* b_psconv1 = (const float*)d_in[8];
    const float* w_psconv2 = (const float*)d_in[9];
    const float* b_psconv2 = (const float*)d_in[10];
    const float* w_pconv1  = (const float*)d_in[11];
    const float* b_pconv1  = (const float*)d_in[12];
    const float* w_pconv2  = (const float*)d_in[13];
    const float* b_pconv2  = (const float*)d_in[14];
    const float* w_fc1 = (const float*)d_in[15];
    const float* b_fc1 = (const float*)d_in[16];
    const float* w_fc2 = (const float*)d_in[17];
    const float* b_fc2 = (const float*)d_in[18];
    const float* w_fc  = (const float*)d_in[19];
    const float* b_fc  = (const float*)d_in[20];
    float* out = (float*)d_out;

    k1<<<324, 256>>>(cloud, ctar, imf,
                     w_pconv1, b_pconv1, w_pconv2, b_pconv2,
                     w_conv1, b_conv1,
                     w_psconv1, b_psconv1,
                     w_psconv2, w_conv2, w_fc1, w_fc2, w_fc);
    k3<<<125, 256>>>(b_conv2, b_psconv2, b_fc1, b_fc2, b_fc, out);
}

// round 6
// speedup vs baseline: 3.7335x; 1.1953x over previous
#include <cuda_runtime.h>
#include <float.h>

#define NPTS 500
#define NP 8
#define NCOL 4000   // NPTS*NP

// ---------------- scratch (device globals) ----------------
__device__ int   g_inds[NCOL];
__device__ int   g_inds_tc[NCOL];
__device__ float g_expw[2 * NCOL];
__device__ float g_inv[2];            // softmax 1/denominator per direction
__device__ float g_cf[NPTS * 128];
__device__ float g_imf[NPTS * 32];
__device__ float g_h1[NPTS * 64];
__device__ float g_hp[NPTS * 256];
// transposed weights (k-major)
__device__ float g_wps1T[128 * 256];
__device__ float g_wps2T[256 * 128];
__device__ float g_wc2T [64 * 128];
__device__ float g_wfc1T[256 * 64];
__device__ float g_wfc2T[160 * 64];
__device__ float g_wfcT [128 * 64];

__device__ __forceinline__ float lrelu(float x) { return x > 0.f ? x : 0.01f * x; }
__device__ __forceinline__ unsigned ordf(float f) {
    unsigned u = __float_as_uint(f);
    return (u & 0x80000000u) ? ~u : (u | 0x80000000u);
}
#define BARW(id) asm volatile("bar.sync %0, %1;" :: "r"(id), "r"(256) : "memory")

// =======================================================================
// Kernel 1:
//   [0,125): dual KNN  |  [125,250): imf^T, H64, cf, h1  |  [250,388): transposes
// =======================================================================
__global__ __launch_bounds__(256) void k1(const float* __restrict__ c,
                                          const float* __restrict__ ct,
                                          const float* __restrict__ imf,
                                          const float* __restrict__ wp1, const float* __restrict__ bp1,
                                          const float* __restrict__ wp2, const float* __restrict__ bp2,
                                          const float* __restrict__ wc1, const float* __restrict__ bc1,
                                          const float* __restrict__ wps1,
                                          const float* __restrict__ wps2,
                                          const float* __restrict__ wc2,
                                          const float* __restrict__ wfc1,
                                          const float* __restrict__ wfc2,
                                          const float* __restrict__ wfc) {
    __shared__ __align__(16) float sb[3008];
    int t = threadIdx.x;

    if (blockIdx.x < 125) {
        // ---------------- KNN ----------------
        float* Pc = sb;          // c  (1500)
        float* Pt = sb + 1504;   // ct (1500)
        for (int i = t; i < 1500; i += 256) { Pc[i] = c[i]; Pt[i] = ct[i]; }
        __syncthreads();

        int warp = t >> 5, lane = t & 31;
        int gw = blockIdx.x * 8 + warp;
        int dir = gw >= NPTS;
        int q = dir ? gw - NPTS : gw;
        const float* Q = dir ? Pt : Pc;
        const float* R = dir ? Pc : Pt;

        float qx = Q[q * 3 + 0], qy = Q[q * 3 + 1], qz = Q[q * 3 + 2];
        float qq = qx * qx + qy * qy + qz * qz;

        float bd[8]; int bi[8];
#pragma unroll
        for (int k = 0; k < 8; k++) { bd[k] = FLT_MAX; bi[k] = 0x3fffffff; }

#pragma unroll 4
        for (int j = lane; j < NPTS; j += 32) {
            float rx = R[j * 3 + 0], ry = R[j * 3 + 1], rz = R[j * 3 + 2];
            float d2 = qq - 2.f * (qx * rx + qy * ry + qz * rz) + (rx * rx + ry * ry + rz * rz);
            if (d2 < bd[7] || (d2 == bd[7] && j < bi[7])) {
                bd[7] = d2; bi[7] = j;
#pragma unroll
                for (int k = 7; k > 0; k--) {
                    if (bd[k] < bd[k - 1] || (bd[k] == bd[k - 1] && bi[k] < bi[k - 1])) {
                        float td = bd[k]; bd[k] = bd[k - 1]; bd[k - 1] = td;
                        int   ti = bi[k]; bi[k] = bi[k - 1]; bi[k - 1] = ti;
                    }
                }
            }
        }

        int*   outi = dir ? g_inds_tc : g_inds;
        float* oute = dir ? (g_expw + NCOL) : g_expw;

#pragma unroll
        for (int s = 0; s < NP; s++) {
            unsigned key = ordf(bd[0]);
            unsigned mk  = __reduce_min_sync(0xffffffffu, key);
            unsigned cand = (key == mk) ? (unsigned)bi[0] : 0xffffffffu;
            unsigned sel  = __reduce_min_sync(0xffffffffu, cand);
            if (lane == 0) {
                outi[q * NP + s] = (int)sel;
                float dx = qx - R[sel * 3 + 0];
                float dy = qy - R[sel * 3 + 1];
                float dz = qz - R[sel * 3 + 2];
                oute[q * NP + s] = expf(-sqrtf(dx * dx + dy * dy + dz * dz));
            }
            if (key == mk && (unsigned)bi[0] == sel) {
#pragma unroll
                for (int k = 0; k < 7; k++) { bd[k] = bd[k + 1]; bi[k] = bi[k + 1]; }
                bd[7] = FLT_MAX; bi[7] = 0x3fffffff;
            }
        }
        return;
    }

    if (blockIdx.x < 250) {
        // ---------------- feature block: 4 points (imf^T, H64, cf, h1) ----------------
        float (*Hs)[64] = (float(*)[64])sb;          // 256 floats
        float (*Is)[32] = (float(*)[32])(sb + 256);  // 128 floats
        int p0 = (blockIdx.x - 125) * 4;
        int warp = t >> 5, lane = t & 31;

        if (t < 128) {
            int lp = t >> 5, chn = t & 31;
            float v = imf[chn * NPTS + (p0 + lp)];
            Is[lp][chn] = v;
            g_imf[(p0 + lp) * 32 + chn] = v;
        }
        {
            int lp = t >> 6, r = t & 63;
            int p = p0 + lp;
            float h = bp1[r] + wp1[r * 3 + 0] * c[p * 3 + 0] + wp1[r * 3 + 1] * c[p * 3 + 1]
                             + wp1[r * 3 + 2] * c[p * 3 + 2];
            Hs[lp][r] = lrelu(h);
        }
        __syncthreads();

        {   // cf = Wp2(128x64) @ H64 + b  -- warp-dot: 8 warps x 16 rows
            float2 hx[4];
#pragma unroll
            for (int cc = 0; cc < 4; cc++) hx[cc] = *(float2*)&Hs[cc][lane * 2];
#pragma unroll 2
            for (int i = 0; i < 16; i++) {
                int r = warp * 16 + i;
                float2 w2 = __ldg((const float2*)(wp2 + r * 64 + lane * 2));
                float p[4];
#pragma unroll
                for (int cc = 0; cc < 4; cc++) p[cc] = w2.x * hx[cc].x + w2.y * hx[cc].y;
#pragma unroll
                for (int off = 16; off; off >>= 1)
#pragma unroll
                    for (int cc = 0; cc < 4; cc++) p[cc] += __shfl_xor_sync(0xffffffffu, p[cc], off);
                if (lane == 0) {
                    float bb = __ldg(bp2 + r);
#pragma unroll
                    for (int cc = 0; cc < 4; cc++)
                        g_cf[(p0 + cc) * 128 + r] = p[cc] + bb;
                }
            }
        }
        {   // h1 = lrelu(Wc1(64x32) @ imf + b)
            float xi[4];
#pragma unroll
            for (int cc = 0; cc < 4; cc++) xi[cc] = Is[cc][lane];
#pragma unroll
            for (int i = 0; i < 8; i++) {
                int r = warp * 8 + i;
                float w = __ldg(wc1 + r * 32 + lane);
                float p[4];
#pragma unroll
                for (int cc = 0; cc < 4; cc++) p[cc] = w * xi[cc];
#pragma unroll
                for (int off = 16; off; off >>= 1)
#pragma unroll
                    for (int cc = 0; cc < 4; cc++) p[cc] += __shfl_xor_sync(0xffffffffu, p[cc], off);
                if (lane == 0) {
                    float bb = __ldg(bc1 + r);
#pragma unroll
                    for (int cc = 0; cc < 4; cc++)
                        g_h1[(p0 + cc) * 64 + r] = lrelu(p[cc] + bb);
                }
            }
        }
        return;
    }

    // ---------------- transpose blocks: one 32x32 tile each ----------------
    {
        int bb = blockIdx.x - 250;
        const float* src; float* dst; int R, C, tile;
        if      (bb < 32)  { src = wps2; dst = g_wps2T; R = 128; C = 256; tile = bb; }
        else if (bb < 40)  { src = wc2;  dst = g_wc2T;  R = 128; C = 64;  tile = bb - 32; }
        else if (bb < 56)  { src = wfc1; dst = g_wfc1T; R = 64;  C = 256; tile = bb - 40; }
        else if (bb < 66)  { src = wfc2; dst = g_wfc2T; R = 64;  C = 160; tile = bb - 56; }
        else if (bb < 74)  { src = wfc;  dst = g_wfcT;  R = 64;  C = 128; tile = bb - 66; }
        else               { src = wps1; dst = g_wps1T; R = 256; C = 128; tile = bb - 74; }
        int tilesC = C / 32;
        int tr = (tile / tilesC) * 32, tc = (tile % tilesC) * 32;
        float (*S)[33] = (float(*)[33])sb;
        int r = t >> 3, q = t & 7;
        float4 v = *(const float4*)(src + (tr + r) * C + tc + q * 4);
        S[r][q * 4 + 0] = v.x; S[r][q * 4 + 1] = v.y; S[r][q * 4 + 2] = v.z; S[r][q * 4 + 3] = v.w;
        __syncthreads();
        float4 o;
        o.x = S[q * 4 + 0][r]; o.y = S[q * 4 + 1][r]; o.z = S[q * 4 + 2][r]; o.w = S[q * 4 + 3][r];
        *(float4*)(dst + (tc + r) * R + tr + q * 4) = o;
    }
}

// =======================================================================
// Kernel 2: [0,125): Hp = lrelu(Wps1 @ cf + b)  (k-sliced, coalesced)
//           [125,127): softmax denominators -> g_inv
// =======================================================================
__global__ __launch_bounds__(256) void k2(const float* __restrict__ bps1) {
    __shared__ __align__(16) float Xs[4][128];
    __shared__ __align__(16) float P[4096];
    int t = threadIdx.x;

    if (blockIdx.x >= 125) {
        int d = blockIdx.x - 125;
        const float* x = g_expw + d * NCOL;
        __shared__ __align__(16) float red[256];
        float s = 0.f;
        for (int i = t; i < NCOL; i += 256) s += x[i];
        red[t] = s; __syncthreads();
        for (int q = 128; q; q >>= 1) { if (t < q) red[t] += red[t + q]; __syncthreads(); }
        if (t == 0) g_inv[d] = 1.f / red[0];
        return;
    }

    int p0 = blockIdx.x * 4;
    if (t < 128) {
        int col = t >> 5, f = t & 31;
        *(float4*)&Xs[col][f * 4] = *(const float4*)&g_cf[(p0 + col) * 128 + f * 4];
    }
    __syncthreads();

    {   // 256 rows x 4 cols, K=128: rq=t&63 (rows rq*4..+3), ks=t>>6 (4 x K=32)
        int rq = t & 63, ks = t >> 6;
        float4 a[4] = {};
        const float* wp = g_wps1T + (ks * 32) * 256 + rq * 4;
#pragma unroll
        for (int kg = 0; kg < 8; kg++) {
            float xk[4][4];
#pragma unroll
            for (int cc = 0; cc < 4; cc++) *(float4*)xk[cc] = *(float4*)&Xs[cc][ks * 32 + kg * 4];
#pragma unroll
            for (int j = 0; j < 4; j++) {
                float4 w4 = *(const float4*)(wp + (kg * 4 + j) * 256);
#pragma unroll
                for (int cc = 0; cc < 4; cc++) {
                    float x = xk[cc][j];
                    a[cc].x += w4.x * x; a[cc].y += w4.y * x; a[cc].z += w4.z * x; a[cc].w += w4.w * x;
                }
            }
        }
#pragma unroll
        for (int cc = 0; cc < 4; cc++)
            *(float4*)&P[(ks * 4 + cc) * 256 + rq * 4] = a[cc];
    }
    __syncthreads();
    for (int o = t; o < 1024; o += 256) {
        int r = o & 255, cc = o >> 8;
        float s = 0;
#pragma unroll
        for (int ks = 0; ks < 4; ks++) s += P[(ks * 4 + cc) * 256 + r];
        g_hp[(p0 + cc) * 256 + r] = lrelu(s + bps1[r]);
    }
}

// =======================================================================
// Kernel 3: 125 blocks x 512 threads x 4 points.
//   WG A (t<256):  Hpbar -> Y2 -> f2        WG B: Hbar -> Y1 -> f1
//   join: out GEMM
// =======================================================================
__global__ __launch_bounds__(512) void k3(const float* __restrict__ bc2,
                                          const float* __restrict__ bps2,
                                          const float* __restrict__ bfc1,
                                          const float* __restrict__ bfc2,
                                          const float* __restrict__ bfc,
                                          float* __restrict__ out) {
    __shared__ __align__(16) int   I0[32];
    __shared__ __align__(16) int   I1[32];
    __shared__ __align__(16) float W0[32];
    __shared__ __align__(16) float W1[32];
    __shared__ __align__(16) float Ws0[4];
    __shared__ __align__(16) float Ws1[4];
    __shared__ __align__(16) float Hb[4][64];
    __shared__ __align__(16) float Hpb[4][256];
    __shared__ __align__(16) float A1[4][256];   // [0:128)=Sf  [128:256)=Cf
    __shared__ __align__(16) float A2[4][160];   // [0:128)=Sfp [128:160)=Im
    __shared__ __align__(16) float Z[4][128];
    __shared__ __align__(16) float PA[4096];
    __shared__ __align__(16) float PB[4096];

    int t = threadIdx.x;
    int wg = t >> 8, ta = t & 255;
    int p0 = blockIdx.x * 4;

    // staging
    if (wg == 0) {
        if (ta < 32) {
            int e = p0 * NP + ta;
            I0[ta] = g_inds[e];    W0[ta] = g_expw[e];
            I1[ta] = g_inds_tc[e]; W1[ta] = g_expw[NCOL + e];
        } else if (ta < 64) {
            int tt = ta - 32;
            int col = tt >> 3, f = tt & 7;
            *(float4*)&A2[col][128 + f * 4] = *(const float4*)&g_imf[(p0 + col) * 32 + f * 4];
        }
    } else {
        if (ta < 128) {
            int col = ta >> 5, f = ta & 31;
            *(float4*)&A1[col][128 + f * 4] = *(const float4*)&g_cf[(p0 + col) * 128 + f * 4];
        }
    }
    __syncthreads();

    if (wg == 0) {
        // ========== chain A: Hpbar -> Y2 -> f2 ==========
        float inv1 = g_inv[1];
        if (ta < 4) {
            float s = 0;
#pragma unroll
            for (int j = 0; j < 8; j++) s += W1[ta * 8 + j];
            Ws1[ta] = 0.125f * inv1 * s;
        }
        {   // Hpbar: r = ta
            int r = ta;
#pragma unroll
            for (int lp = 0; lp < 4; lp++) {
                float s = 0;
#pragma unroll
                for (int j = 0; j < 8; j++) s += W1[lp * 8 + j] * g_hp[I1[lp * 8 + j] * 256 + r];
                Hpb[lp][r] = 0.125f * inv1 * s;
            }
        }
        BARW(1);

        {   // Y2: 128 rows, K=256; rq=ta&31, ks=ta>>5 (8 x K=32)
            int rq = ta & 31, ks = ta >> 5;
            float4 a[4] = {};
            const float* wp = g_wps2T + (ks * 32) * 128 + rq * 4;
#pragma unroll
            for (int kg = 0; kg < 8; kg++) {
                float xk[4][4];
#pragma unroll
                for (int cc = 0; cc < 4; cc++) *(float4*)xk[cc] = *(float4*)&Hpb[cc][ks * 32 + kg * 4];
#pragma unroll
                for (int j = 0; j < 4; j++) {
                    float4 w4 = *(const float4*)(wp + (kg * 4 + j) * 128);
#pragma unroll
                    for (int cc = 0; cc < 4; cc++) {
                        float x = xk[cc][j];
                        a[cc].x += w4.x * x; a[cc].y += w4.y * x; a[cc].z += w4.z * x; a[cc].w += w4.w * x;
                    }
                }
            }
#pragma unroll
            for (int cc = 0; cc < 4; cc++)
                *(float4*)&PA[(ks * 4 + cc) * 128 + rq * 4] = a[cc];
        }
        BARW(1);
        for (int o = ta; o < 512; o += 256) {   // -> Sfp (A2 low)
            int r = o & 127, cc = o >> 7;
            float s = 0;
#pragma unroll
            for (int ks = 0; ks < 8; ks++) s += PA[(ks * 4 + cc) * 128 + r];
            A2[cc][r] = s + bps2[r] * Ws1[cc];
        }
        BARW(1);

        {   // f2: 64 rows, K=160; rq=ta&15, ks=ta>>4 (16 x K=10)
            int rq = ta & 15, ks = ta >> 4;
            float4 a[4] = {};
            const float* wp = g_wfc2T + (ks * 10) * 64 + rq * 4;
#pragma unroll
            for (int k = 0; k < 10; k++) {
                float4 w4 = *(const float4*)(wp + k * 64);
                int kk = ks * 10 + k;
#pragma unroll
                for (int cc = 0; cc < 4; cc++) {
                    float x = A2[cc][kk];
                    a[cc].x += w4.x * x; a[cc].y += w4.y * x; a[cc].z += w4.z * x; a[cc].w += w4.w * x;
                }
            }
#pragma unroll
            for (int cc = 0; cc < 4; cc++)
                *(float4*)&PA[(ks * 4 + cc) * 64 + rq * 4] = a[cc];
        }
        BARW(1);
        {   // -> Z[:,ch]
            int ch = ta & 63, cc = ta >> 6;
            float s = 0;
#pragma unroll
            for (int ks = 0; ks < 16; ks++) s += PA[(ks * 4 + cc) * 64 + ch];
            Z[cc][ch] = lrelu(s + bfc2[ch]);
        }
    } else {
        // ========== chain B: Hbar -> Y1 -> f1 ==========
        float inv0 = g_inv[0];
        if (ta < 4) {
            float s = 0;
#pragma unroll
            for (int j = 0; j < 8; j++) s += W0[ta * 8 + j];
            Ws0[ta] = 0.125f * inv0 * s;
        }
        {   // Hbar
            int lp = ta >> 6, r = ta & 63;
            float s = 0;
#pragma unroll
            for (int j = 0; j < 8; j++) s += W0[lp * 8 + j] * g_h1[I0[lp * 8 + j] * 64 + r];
            Hb[lp][r] = 0.125f * inv0 * s;
        }
        BARW(2);

        {   // Y1: 128 rows, K=64; rq=ta&31, ks=ta>>5 (8 x K=8)
            int rq = ta & 31, ks = ta >> 5;
            float4 a[4] = {};
            const float* wp = g_wc2T + (ks * 8) * 128 + rq * 4;
#pragma unroll
            for (int kg = 0; kg < 2; kg++) {
                float xk[4][4];
#pragma unroll
                for (int cc = 0; cc < 4; cc++) *(float4*)xk[cc] = *(float4*)&Hb[cc][ks * 8 + kg * 4];
#pragma unroll
                for (int j = 0; j < 4; j++) {
                    float4 w4 = *(const float4*)(wp + (kg * 4 + j) * 128);
#pragma unroll
                    for (int cc = 0; cc < 4; cc++) {
                        float x = xk[cc][j];
                        a[cc].x += w4.x * x; a[cc].y += w4.y * x; a[cc].z += w4.z * x; a[cc].w += w4.w * x;
                    }
                }
            }
#pragma unroll
            for (int cc = 0; cc < 4; cc++)
                *(float4*)&PB[(ks * 4 + cc) * 128 + rq * 4] = a[cc];
        }
        BARW(2);
        for (int o = ta; o < 512; o += 256) {   // -> Sf (A1 low)
            int r = o & 127, cc = o >> 7;
            float s = 0;
#pragma unroll
            for (int ks = 0; ks < 8; ks++) s += PB[(ks * 4 + cc) * 128 + r];
            A1[cc][r] = s + bc2[r] * Ws0[cc];
        }
        BARW(2);

        {   // f1: 64 rows, K=256; rq=ta&15, ks=ta>>4 (16 x K=16)
            int rq = ta & 15, ks = ta >> 4;
            float4 a[4] = {};
            const float* wp = g_wfc1T + (ks * 16) * 64 + rq * 4;
#pragma unroll
            for (int kg = 0; kg < 4; kg++) {
                float xk[4][4];
#pragma unroll
                for (int cc = 0; cc < 4; cc++) *(float4*)xk[cc] = *(float4*)&A1[cc][ks * 16 + kg * 4];
#pragma unroll
                for (int j = 0; j < 4; j++) {
                    float4 w4 = *(const float4*)(wp + (kg * 4 + j) * 64);
#pragma unroll
                    for (int cc = 0; cc < 4; cc++) {
                        float x = xk[cc][j];
                        a[cc].x += w4.x * x; a[cc].y += w4.y * x; a[cc].z += w4.z * x; a[cc].w += w4.w * x;
                    }
                }
            }
#pragma unroll
            for (int cc = 0; cc < 4; cc++)
                *(float4*)&PB[(ks * 4 + cc) * 64 + rq * 4] = a[cc];
        }
        BARW(2);
        {   // -> Z[:,64+ch]
            int ch = ta & 63, cc = ta >> 6;
            float s = 0;
#pragma unroll
            for (int ks = 0; ks < 16; ks++) s += PB[(ks * 4 + cc) * 64 + ch];
            Z[cc][64 + ch] = lrelu(s + bfc1[ch]);
        }
    }
    __syncthreads();

    // out: 64 rows, K=128 over Z — WG A only
    if (wg == 0) {
        {
            int rq = ta & 15, ks = ta >> 4;   // 16 x K=8
            float4 a[4] = {};
            const float* wp = g_wfcT + (ks * 8) * 64 + rq * 4;
#pragma unroll
            for (int kg = 0; kg < 2; kg++) {
                float xk[4][4];
#pragma unroll
                for (int cc = 0; cc < 4; cc++) *(float4*)xk[cc] = *(float4*)&Z[cc][ks * 8 + kg * 4];
#pragma unroll
                for (int j = 0; j < 4; j++) {
                    float4 w4 = *(const float4*)(wp + (kg * 4 + j) * 64);
#pragma unroll
                    for (int cc = 0; cc < 4; cc++) {
                        float x = xk[cc][j];
                        a[cc].x += w4.x * x; a[cc].y += w4.y * x; a[cc].z += w4.z * x; a[cc].w += w4.w * x;
                    }
                }
            }
#pragma unroll
            for (int cc = 0; cc < 4; cc++)
                *(float4*)&PA[(ks * 4 + cc) * 64 + rq * 4] = a[cc];
        }
        BARW(1);
        {
            int ch = ta & 63, cc = ta >> 6;
            float s = 0;
#pragma unroll
            for (int ks = 0; ks < 16; ks++) s += PA[(ks * 4 + cc) * 64 + ch];
            out[ch * NPTS + (p0 + cc)] = s + bfc[ch];
        }
    }
}

// ---------------- launch ----------------
extern "C" void kernel_launch(void* const* d_in, const int* in_sizes, int n_in,
                              void* d_out, int out_size) {
    const float* imf   = (const float*)d_in[0];
    const float* cloud = (const float*)d_in[1];
    const float* ctar  = (const float*)d_in[2];
    const float* w_conv1   = (const float*)d_in[3];
    const float* b_conv1   = (const float*)d_in[4];
    const float* w_conv2   = (const float*)d_in[5];
    const float* b_conv2   = (const float*)d_in[6];
    const float* w_psconv1 = (const float*)d_in[7];
    const float* b_psconv1 = (const float*)d_in[8];
    const float* w_psconv2 = (const float*)d_in[9];
    const float* b_psconv2 = (const float*)d_in[10];
    const float* w_pconv1  = (const float*)d_in[11];
    const float* b_pconv1  = (const float*)d_in[12];
    const float* w_pconv2  = (const float*)d_in[13];
    const float* b_pconv2  = (const float*)d_in[14];
    const float* w_fc1 = (const float*)d_in[15];
    const float* b_fc1 = (const float*)d_in[16];
    const float* w_fc2 = (const float*)d_in[17];
    const float* b_fc2 = (const float*)d_in[18];
    const float* w_fc  = (const float*)d_in[19];
    const float* b_fc  = (const float*)d_in[20];
    float* out = (float*)d_out;

    k1<<<356, 256>>>(cloud, ctar, imf,
                     w_pconv1, b_pconv1, w_pconv2, b_pconv2,
                     w_conv1, b_conv1,
                     w_psconv1, w_psconv2, w_conv2, w_fc1, w_fc2, w_fc);
    k2<<<127, 256>>>(b_psconv1);
    k3<<<125, 512>>>(b_conv2, b_psconv2, b_fc1, b_fc2, b_fc, out);
}

// round 7
// speedup vs baseline: 4.0241x; 1.0779x over previous
#include <cuda_runtime.h>
#include <float.h>

#define NPTS 500
#define NP 8
#define NCOL 4000   // NPTS*NP

// ---------------- scratch (device globals) ----------------
__device__ int   g_inds[NCOL];
__device__ int   g_inds_tc[NCOL];
__device__ float g_expw[2 * NCOL];
__device__ float g_inv[2];            // softmax 1/denominator per direction
__device__ float g_cf[NPTS * 128];
__device__ float g_imf[NPTS * 32];
__device__ float g_h1[NPTS * 64];
__device__ float g_hp[NPTS * 256];
// transposed weights (k-major)
__device__ float g_wps1T[128 * 256];
__device__ float g_wps2T[256 * 128];
__device__ float g_wc2T [64 * 128];
__device__ float g_wfc1T[256 * 64];
__device__ float g_wfc2T[160 * 64];
__device__ float g_wfcT [128 * 64];

__device__ __forceinline__ float lrelu(float x) { return x > 0.f ? x : 0.01f * x; }
__device__ __forceinline__ unsigned ordf(float f) {
    unsigned u = __float_as_uint(f);
    return (u & 0x80000000u) ? ~u : (u | 0x80000000u);
}
#define BARW(id) asm volatile("bar.sync %0, %1;" :: "r"(id), "r"(256) : "memory")

// =======================================================================
// Kernel 1:
//   [0,125): dual KNN (warp/query, vectorized, ballot extraction)
//   [125,250): imf^T, H64, cf, h1 via smem-transposed weights (no shuffles)
//   [250,356): 32x32 tiled weight transposes
// =======================================================================
__global__ __launch_bounds__(256) void k1(const float* __restrict__ c,
                                          const float* __restrict__ ct,
                                          const float* __restrict__ imf,
                                          const float* __restrict__ wp1, const float* __restrict__ bp1,
                                          const float* __restrict__ wp2, const float* __restrict__ bp2,
                                          const float* __restrict__ wc1, const float* __restrict__ bc1,
                                          const float* __restrict__ wps1,
                                          const float* __restrict__ wps2,
                                          const float* __restrict__ wc2,
                                          const float* __restrict__ wfc1,
                                          const float* __restrict__ wfc2,
                                          const float* __restrict__ wfc) {
    __shared__ __align__(16) float sb[11008];   // 43 KB, carved per block role
    int t = threadIdx.x;
    int bid = blockIdx.x;

    if (bid < 125) {
        // ---------------- KNN: 8 query-dirs per block ----------------
        // refs: dir0 -> ct at sb[0], dir1 -> c at sb[1504]
        if (bid <= 62) for (int i = t; i < 1500; i += 256) sb[i] = ct[i];
        if (bid >= 62) for (int i = t; i < 1500; i += 256) sb[1504 + i] = c[i];
        int* selS = (int*)(sb + 10720);          // [8 warps][8]
        __syncthreads();

        int warp = t >> 5, lane = t & 31;
        int gw = bid * 8 + warp;
        int dir = gw >= NPTS;
        int q = dir ? gw - NPTS : gw;
        const float* Qg = dir ? ct : c;
        float qx = __ldg(Qg + q * 3 + 0), qy = __ldg(Qg + q * 3 + 1), qz = __ldg(Qg + q * 3 + 2);
        float qq = qx * qx + qy * qy + qz * qz;

        const float* R = sb + (dir ? 1504 : 0);
        int j0 = lane * 16;
        int cnt = (j0 + 16 <= NPTS) ? 16 : (NPTS - j0);   // lane 31: 4

        float bd[8]; int bi[8];
#pragma unroll
        for (int k = 0; k < 8; k++) { bd[k] = FLT_MAX; bi[k] = 0x3fffffff; }

#pragma unroll
        for (int h8 = 0; h8 < 2; h8++) {
            float f[24];
            const float4* rp = (const float4*)(R + (j0 + h8 * 8) * 3);
#pragma unroll
            for (int v = 0; v < 6; v++) *(float4*)&f[v * 4] = rp[v];
#pragma unroll
            for (int jj = 0; jj < 8; jj++) {
                float rx = f[jj * 3 + 0], ry = f[jj * 3 + 1], rz = f[jj * 3 + 2];
                float d2 = qq - 2.f * (qx * rx + qy * ry + qz * rz) + (rx * rx + ry * ry + rz * rz);
                int rel = h8 * 8 + jj;
                int j = j0 + rel;
                if (rel < cnt && (d2 < bd[7] || (d2 == bd[7] && j < bi[7]))) {
                    bd[7] = d2; bi[7] = j;
#pragma unroll
                    for (int k = 7; k > 0; k--) {
                        if (bd[k] < bd[k - 1] || (bd[k] == bd[k - 1] && bi[k] < bi[k - 1])) {
                            float td = bd[k]; bd[k] = bd[k - 1]; bd[k - 1] = td;
                            int   ti = bi[k]; bi[k] = bi[k - 1]; bi[k - 1] = ti;
                        }
                    }
                }
            }
        }

        // extraction: REDUX min + ballot; lane blocks are index-ordered so
        // lowest matching lane == lowest index.
#pragma unroll
        for (int s = 0; s < NP; s++) {
            unsigned key = ordf(bd[0]);
            unsigned mk  = __reduce_min_sync(0xffffffffu, key);
            unsigned mask = __ballot_sync(0xffffffffu, key == mk);
            int owner = __ffs(mask) - 1;
            if (lane == owner) {
                selS[warp * 8 + s] = bi[0];
#pragma unroll
                for (int k = 0; k < 7; k++) { bd[k] = bd[k + 1]; bi[k] = bi[k + 1]; }
                bd[7] = FLT_MAX; bi[7] = 0x3fffffff;
            }
        }
        __syncwarp();

        int*   outi = dir ? g_inds_tc : g_inds;
        float* oute = dir ? (g_expw + NCOL) : g_expw;
        if (lane < NP) {
            int mi = selS[warp * 8 + lane];
            float dx = qx - R[mi * 3 + 0];
            float dy = qy - R[mi * 3 + 1];
            float dz = qz - R[mi * 3 + 2];
            outi[q * NP + lane] = mi;
            oute[q * NP + lane] = expf(-sqrtf(dx * dx + dy * dy + dz * dz));
        }
        return;
    }

    if (bid < 250) {
        // ---------------- feature block: 4 points (imf^T, H64, cf, h1) ----------------
        float* Hs = sb;            // [4][64]
        float* Is = sb + 256;      // [4][32]
        float* Wt = sb + 384;      // [64][129]  wp2 transposed, padded
        float* Wc = sb + 8640;     // [32][65]   wc1 transposed, padded
        int p0 = (bid - 125) * 4;

        // stage wp2 -> Wt[k][r]
        for (int e = t; e < 2048; e += 256) {
            float4 v = __ldg((const float4*)(wp2 + e * 4));
            int r = e >> 4, k0 = (e & 15) * 4;
            Wt[(k0 + 0) * 129 + r] = v.x;
            Wt[(k0 + 1) * 129 + r] = v.y;
            Wt[(k0 + 2) * 129 + r] = v.z;
            Wt[(k0 + 3) * 129 + r] = v.w;
        }
        // stage wc1 -> Wc[k][r]
        for (int e = t; e < 512; e += 256) {
            float4 v = __ldg((const float4*)(wc1 + e * 4));
            int r = e >> 3, k0 = (e & 7) * 4;
            Wc[(k0 + 0) * 65 + r] = v.x;
            Wc[(k0 + 1) * 65 + r] = v.y;
            Wc[(k0 + 2) * 65 + r] = v.z;
            Wc[(k0 + 3) * 65 + r] = v.w;
        }
        if (t < 128) {                       // imf cols + transpose out
            int lp = t >> 5, chn = t & 31;
            float v = imf[chn * NPTS + (p0 + lp)];
            Is[lp * 32 + chn] = v;
            g_imf[(p0 + lp) * 32 + chn] = v;
        }
        {                                    // H64 = lrelu(Wp1 @ c + b)
            int lp = t >> 6, r = t & 63;
            int p = p0 + lp;
            float h = bp1[r] + wp1[r * 3 + 0] * c[p * 3 + 0] + wp1[r * 3 + 1] * c[p * 3 + 1]
                             + wp1[r * 3 + 2] * c[p * 3 + 2];
            Hs[lp * 64 + r] = lrelu(h);
        }
        __syncthreads();

        {   // cf: thread-per-output x2 cols. r=t&127, cols {2h, 2h+1}
            int r = t & 127, h = t >> 7;
            const float* x0 = Hs + (2 * h) * 64;
            const float* x1 = Hs + (2 * h + 1) * 64;
            float a0 = 0.f, a1 = 0.f;
#pragma unroll 8
            for (int k = 0; k < 64; k++) {
                float w = Wt[k * 129 + r];
                a0 += w * x0[k];
                a1 += w * x1[k];
            }
            float b = __ldg(bp2 + r);
            g_cf[(p0 + 2 * h) * 128 + r]     = a0 + b;
            g_cf[(p0 + 2 * h + 1) * 128 + r] = a1 + b;
        }
        {   // h1: thread-per-output. r=t&63, cc=t>>6
            int r = t & 63, cc = t >> 6;
            const float* xi = Is + cc * 32;
            float a = 0.f;
#pragma unroll 8
            for (int k = 0; k < 32; k++) a += Wc[k * 65 + r] * xi[k];
            g_h1[(p0 + cc) * 64 + r] = lrelu(a + __ldg(bc1 + r));
        }
        return;
    }

    // ---------------- transpose blocks: one 32x32 tile each ----------------
    {
        int bb = bid - 250;
        const float* src; float* dst; int R, C, tile;
        if      (bb < 32)  { src = wps2; dst = g_wps2T; R = 128; C = 256; tile = bb; }
        else if (bb < 40)  { src = wc2;  dst = g_wc2T;  R = 128; C = 64;  tile = bb - 32; }
        else if (bb < 56)  { src = wfc1; dst = g_wfc1T; R = 64;  C = 256; tile = bb - 40; }
        else if (bb < 66)  { src = wfc2; dst = g_wfc2T; R = 64;  C = 160; tile = bb - 56; }
        else if (bb < 74)  { src = wfc;  dst = g_wfcT;  R = 64;  C = 128; tile = bb - 66; }
        else               { src = wps1; dst = g_wps1T; R = 256; C = 128; tile = bb - 74; }
        int tilesC = C / 32;
        int tr = (tile / tilesC) * 32, tc = (tile % tilesC) * 32;
        float (*S)[33] = (float(*)[33])sb;
        int r = t >> 3, q = t & 7;
        float4 v = *(const float4*)(src + (tr + r) * C + tc + q * 4);
        S[r][q * 4 + 0] = v.x; S[r][q * 4 + 1] = v.y; S[r][q * 4 + 2] = v.z; S[r][q * 4 + 3] = v.w;
        __syncthreads();
        float4 o;
        o.x = S[q * 4 + 0][r]; o.y = S[q * 4 + 1][r]; o.z = S[q * 4 + 2][r]; o.w = S[q * 4 + 3][r];
        *(float4*)(dst + (tc + r) * R + tr + q * 4) = o;
    }
}

// =======================================================================
// Kernel 2: [0,125): Hp = lrelu(Wps1 @ cf + b)  (k-sliced, coalesced)
//           [125,127): softmax denominators -> g_inv
// =======================================================================
__global__ __launch_bounds__(256) void k2(const float* __restrict__ bps1) {
    __shared__ __align__(16) float Xs[4][128];
    __shared__ __align__(16) float P[4096];
    int t = threadIdx.x;

    if (blockIdx.x >= 125) {
        int d = blockIdx.x - 125;
        const float* x = g_expw + d * NCOL;
        __shared__ __align__(16) float red[256];
        float s = 0.f;
        for (int i = t; i < NCOL; i += 256) s += x[i];
        red[t] = s; __syncthreads();
        for (int q = 128; q; q >>= 1) { if (t < q) red[t] += red[t + q]; __syncthreads(); }
        if (t == 0) g_inv[d] = 1.f / red[0];
        return;
    }

    int p0 = blockIdx.x * 4;
    if (t < 128) {
        int col = t >> 5, f = t & 31;
        *(float4*)&Xs[col][f * 4] = *(const float4*)&g_cf[(p0 + col) * 128 + f * 4];
    }
    __syncthreads();

    {   // 256 rows x 4 cols, K=128: rq=t&63, ks=t>>6 (4 x K=32)
        int rq = t & 63, ks = t >> 6;
        float4 a[4] = {};
        const float* wp = g_wps1T + (ks * 32) * 256 + rq * 4;
#pragma unroll
        for (int kg = 0; kg < 8; kg++) {
            float xk[4][4];
#pragma unroll
            for (int cc = 0; cc < 4; cc++) *(float4*)xk[cc] = *(float4*)&Xs[cc][ks * 32 + kg * 4];
#pragma unroll
            for (int j = 0; j < 4; j++) {
                float4 w4 = *(const float4*)(wp + (kg * 4 + j) * 256);
#pragma unroll
                for (int cc = 0; cc < 4; cc++) {
                    float x = xk[cc][j];
                    a[cc].x += w4.x * x; a[cc].y += w4.y * x; a[cc].z += w4.z * x; a[cc].w += w4.w * x;
                }
            }
        }
#pragma unroll
        for (int cc = 0; cc < 4; cc++)
            *(float4*)&P[(ks * 4 + cc) * 256 + rq * 4] = a[cc];
    }
    __syncthreads();
    for (int o = t; o < 1024; o += 256) {
        int r = o & 255, cc = o >> 8;
        float s = 0;
#pragma unroll
        for (int ks = 0; ks < 4; ks++) s += P[(ks * 4 + cc) * 256 + r];
        g_hp[(p0 + cc) * 256 + r] = lrelu(s + bps1[r]);
    }
}

// =======================================================================
// Kernel 3: 125 blocks x 512 threads x 4 points (WG-specialized chains)
// =======================================================================
__global__ __launch_bounds__(512) void k3(const float* __restrict__ bc2,
                                          const float* __restrict__ bps2,
                                          const float* __restrict__ bfc1,
                                          const float* __restrict__ bfc2,
                                          const float* __restrict__ bfc,
                                          float* __restrict__ out) {
    __shared__ __align__(16) int   I0[32];
    __shared__ __align__(16) int   I1[32];
    __shared__ __align__(16) float W0[32];
    __shared__ __align__(16) float W1[32];
    __shared__ __align__(16) float Ws0[4];
    __shared__ __align__(16) float Ws1[4];
    __shared__ __align__(16) float Hb[4][64];
    __shared__ __align__(16) float Hpb[4][256];
    __shared__ __align__(16) float A1[4][256];
    __shared__ __align__(16) float A2[4][160];
    __shared__ __align__(16) float Z[4][128];
    __shared__ __align__(16) float PA[4096];
    __shared__ __align__(16) float PB[4096];

    int t = threadIdx.x;
    int wg = t >> 8, ta = t & 255;
    int p0 = blockIdx.x * 4;

    if (wg == 0) {
        if (ta < 32) {
            int e = p0 * NP + ta;
            I0[ta] = g_inds[e];    W0[ta] = g_expw[e];
            I1[ta] = g_inds_tc[e]; W1[ta] = g_expw[NCOL + e];
        } else if (ta < 64) {
            int tt = ta - 32;
            int col = tt >> 3, f = tt & 7;
            *(float4*)&A2[col][128 + f * 4] = *(const float4*)&g_imf[(p0 + col) * 32 + f * 4];
        }
    } else {
        if (ta < 128) {
            int col = ta >> 5, f = ta & 31;
            *(float4*)&A1[col][128 + f * 4] = *(const float4*)&g_cf[(p0 + col) * 128 + f * 4];
        }
    }
    __syncthreads();

    if (wg == 0) {
        float inv1 = g_inv[1];
        if (ta < 4) {
            float s = 0;
#pragma unroll
            for (int j = 0; j < 8; j++) s += W1[ta * 8 + j];
            Ws1[ta] = 0.125f * inv1 * s;
        }
        {
            int r = ta;
#pragma unroll
            for (int lp = 0; lp < 4; lp++) {
                float s = 0;
#pragma unroll
                for (int j = 0; j < 8; j++) s += W1[lp * 8 + j] * g_hp[I1[lp * 8 + j] * 256 + r];
                Hpb[lp][r] = 0.125f * inv1 * s;
            }
        }
        BARW(1);

        {
            int rq = ta & 31, ks = ta >> 5;
            float4 a[4] = {};
            const float* wp = g_wps2T + (ks * 32) * 128 + rq * 4;
#pragma unroll
            for (int kg = 0; kg < 8; kg++) {
                float xk[4][4];
#pragma unroll
                for (int cc = 0; cc < 4; cc++) *(float4*)xk[cc] = *(float4*)&Hpb[cc][ks * 32 + kg * 4];
#pragma unroll
                for (int j = 0; j < 4; j++) {
                    float4 w4 = *(const float4*)(wp + (kg * 4 + j) * 128);
#pragma unroll
                    for (int cc = 0; cc < 4; cc++) {
                        float x = xk[cc][j];
                        a[cc].x += w4.x * x; a[cc].y += w4.y * x; a[cc].z += w4.z * x; a[cc].w += w4.w * x;
                    }
                }
            }
#pragma unroll
            for (int cc = 0; cc < 4; cc++)
                *(float4*)&PA[(ks * 4 + cc) * 128 + rq * 4] = a[cc];
        }
        BARW(1);
        for (int o = ta; o < 512; o += 256) {
            int r = o & 127, cc = o >> 7;
            float s = 0;
#pragma unroll
            for (int ks = 0; ks < 8; ks++) s += PA[(ks * 4 + cc) * 128 + r];
            A2[cc][r] = s + bps2[r] * Ws1[cc];
        }
        BARW(1);

        {
            int rq = ta & 15, ks = ta >> 4;
            float4 a[4] = {};
            const float* wp = g_wfc2T + (ks * 10) * 64 + rq * 4;
#pragma unroll
            for (int k = 0; k < 10; k++) {
                float4 w4 = *(const float4*)(wp + k * 64);
                int kk = ks * 10 + k;
#pragma unroll
                for (int cc = 0; cc < 4; cc++) {
                    float x = A2[cc][kk];
                    a[cc].x += w4.x * x; a[cc].y += w4.y * x; a[cc].z += w4.z * x; a[cc].w += w4.w * x;
                }
            }
#pragma unroll
            for (int cc = 0; cc < 4; cc++)
                *(float4*)&PA[(ks * 4 + cc) * 64 + rq * 4] = a[cc];
        }
        BARW(1);
        {
            int ch = ta & 63, cc = ta >> 6;
            float s = 0;
#pragma unroll
            for (int ks = 0; ks < 16; ks++) s += PA[(ks * 4 + cc) * 64 + ch];
            Z[cc][ch] = lrelu(s + bfc2[ch]);
        }
    } else {
        float inv0 = g_inv[0];
        if (ta < 4) {
            float s = 0;
#pragma unroll
            for (int j = 0; j < 8; j++) s += W0[ta * 8 + j];
            Ws0[ta] = 0.125f * inv0 * s;
        }
        {
            int lp = ta >> 6, r = ta & 63;
            float s = 0;
#pragma unroll
            for (int j = 0; j < 8; j++) s += W0[lp * 8 + j] * g_h1[I0[lp * 8 + j] * 64 + r];
            Hb[lp][r] = 0.125f * inv0 * s;
        }
        BARW(2);

        {
            int rq = ta & 31, ks = ta >> 5;
            float4 a[4] = {};
            const float* wp = g_wc2T + (ks * 8) * 128 + rq * 4;
#pragma unroll
            for (int kg = 0; kg < 2; kg++) {
                float xk[4][4];
#pragma unroll
                for (int cc = 0; cc < 4; cc++) *(float4*)xk[cc] = *(float4*)&Hb[cc][ks * 8 + kg * 4];
#pragma unroll
                for (int j = 0; j < 4; j++) {
                    float4 w4 = *(const float4*)(wp + (kg * 4 + j) * 128);
#pragma unroll
                    for (int cc = 0; cc < 4; cc++) {
                        float x = xk[cc][j];
                        a[cc].x += w4.x * x; a[cc].y += w4.y * x; a[cc].z += w4.z * x; a[cc].w += w4.w * x;
                    }
                }
            }
#pragma unroll
            for (int cc = 0; cc < 4; cc++)
                *(float4*)&PB[(ks * 4 + cc) * 128 + rq * 4] = a[cc];
        }
        BARW(2);
        for (int o = ta; o < 512; o += 256) {
            int r = o & 127, cc = o >> 7;
            float s = 0;
#pragma unroll
            for (int ks = 0; ks < 8; ks++) s += PB[(ks * 4 + cc) * 128 + r];
            A1[cc][r] = s + bc2[r] * Ws0[cc];
        }
        BARW(2);

        {
            int rq = ta & 15, ks = ta >> 4;
            float4 a[4] = {};
            const float* wp = g_wfc1T + (ks * 16) * 64 + rq * 4;
#pragma unroll
            for (int kg = 0; kg < 4; kg++) {
                float xk[4][4];
#pragma unroll
                for (int cc = 0; cc < 4; cc++) *(float4*)xk[cc] = *(float4*)&A1[cc][ks * 16 + kg * 4];
#pragma unroll
                for (int j = 0; j < 4; j++) {
                    float4 w4 = *(const float4*)(wp + (kg * 4 + j) * 64);
#pragma unroll
                    for (int cc = 0; cc < 4; cc++) {
                        float x = xk[cc][j];
                        a[cc].x += w4.x * x; a[cc].y += w4.y * x; a[cc].z += w4.z * x; a[cc].w += w4.w * x;
                    }
                }
            }
#pragma unroll
            for (int cc = 0; cc < 4; cc++)
                *(float4*)&PB[(ks * 4 + cc) * 64 + rq * 4] = a[cc];
        }
        BARW(2);
        {
            int ch = ta & 63, cc = ta >> 6;
            float s = 0;
#pragma unroll
            for (int ks = 0; ks < 16; ks++) s += PB[(ks * 4 + cc) * 64 + ch];
            Z[cc][64 + ch] = lrelu(s + bfc1[ch]);
        }
    }
    __syncthreads();

    if (wg == 0) {
        {
            int rq = ta & 15, ks = ta >> 4;
            float4 a[4] = {};
            const float* wp = g_wfcT + (ks * 8) * 64 + rq * 4;
#pragma unroll
            for (int kg = 0; kg < 2; kg++) {
                float xk[4][4];
#pragma unroll
                for (int cc = 0; cc < 4; cc++) *(float4*)xk[cc] = *(float4*)&Z[cc][ks * 8 + kg * 4];
#pragma unroll
                for (int j = 0; j < 4; j++) {
                    float4 w4 = *(const float4*)(wp + (kg * 4 + j) * 64);
#pragma unroll
                    for (int cc = 0; cc < 4; cc++) {
                        float x = xk[cc][j];
                        a[cc].x += w4.x * x; a[cc].y += w4.y * x; a[cc].z += w4.z * x; a[cc].w += w4.w * x;
                    }
                }
            }
#pragma unroll
            for (int cc = 0; cc < 4; cc++)
                *(float4*)&PA[(ks * 4 + cc) * 64 + rq * 4] = a[cc];
        }
        BARW(1);
        {
            int ch = ta & 63, cc = ta >> 6;
            float s = 0;
#pragma unroll
            for (int ks = 0; ks < 16; ks++) s += PA[(ks * 4 + cc) * 64 + ch];
            out[ch * NPTS + (p0 + cc)] = s + bfc[ch];
        }
    }
}

// ---------------- launch ----------------
extern "C" void kernel_launch(void* const* d_in, const int* in_sizes, int n_in,
                              void* d_out, int out_size) {
    const float* imf   = (const float*)d_in[0];
    const float* cloud = (const float*)d_in[1];
    const float* ctar  = (const float*)d_in[2];
    const float* w_conv1   = (const float*)d_in[3];
    const float* b_conv1   = (const float*)d_in[4];
    const float* w_conv2   = (const float*)d_in[5];
    const float* b_conv2   = (const float*)d_in[6];
    const float* w_psconv1 = (const float*)d_in[7];
    const float* b_psconv1 = (const float*)d_in[8];
    const float* w_psconv2 = (const float*)d_in[9];
    const float* b_psconv2 = (const float*)d_in[10];
    const float* w_pconv1  = (const float*)d_in[11];
    const float* b_pconv1  = (const float*)d_in[12];
    const float* w_pconv2  = (const float*)d_in[13];
    const float* b_pconv2  = (const float*)d_in[14];
    const float* w_fc1 = (const float*)d_in[15];
    const float* b_fc1 = (const float*)d_in[16];
    const float* w_fc2 = (const float*)d_in[17];
    const float* b_fc2 = (const float*)d_in[18];
    const float* w_fc  = (const float*)d_in[19];
    const float* b_fc  = (const float*)d_in[20];
    float* out = (float*)d_out;

    k1<<<356, 256>>>(cloud, ctar, imf,
                     w_pconv1, b_pconv1, w_pconv2, b_pconv2,
                     w_conv1, b_conv1,
                     w_psconv1, w_psconv2, w_conv2, w_fc1, w_fc2, w_fc);
    k2<<<127, 256>>>(b_psconv1);
    k3<<<125, 512>>>(b_conv2, b_psconv2, b_fc1, b_fc2, b_fc, out);
}

// round 8
// speedup vs baseline: 4.3329x; 1.0767x over previous
#include <cuda_runtime.h>
#include <float.h>

#define NPTS 500
#define NP 8
#define NCOL 4000
#define NBLK 125

// ---------------- scratch (device globals) ----------------
__device__ int   g_inds[NCOL];
__device__ int   g_inds_tc[NCOL];
__device__ float g_expw[2 * NCOL];
__device__ float g_psum[1000];        // per-query exp sums
__device__ float g_cf[NPTS * 128];
__device__ float g_imf[NPTS * 32];
__device__ float g_h1[NPTS * 64];
__device__ float g_hp[NPTS * 256];
__device__ float g_wps1T[128 * 256];
__device__ float g_wps2T[256 * 128];
__device__ float g_wc2T [64 * 128];
__device__ float g_wfc1T[256 * 64];
__device__ float g_wfc2T[160 * 64];
__device__ float g_wfcT [128 * 64];
// software grid barrier state (must return to {0,0} after each launch)
__device__ int            g_ctr = 0;
__device__ volatile int   g_sense = 0;

__device__ __forceinline__ float lrelu(float x) { return x > 0.f ? x : 0.01f * x; }
__device__ __forceinline__ unsigned ordf(float f) {
    unsigned u = __float_as_uint(f);
    return (u & 0x80000000u) ? ~u : (u | 0x80000000u);
}
#define BARW(id) asm volatile("bar.sync %0, %1;" :: "r"(id), "r"(256) : "memory")

// sense-reversing grid barrier; called exactly twice per launch (even -> state restored)
__device__ __forceinline__ void gbar(int phase) {
    __threadfence();
    __syncthreads();
    if (threadIdx.x == 0) {
        if (atomicAdd(&g_ctr, 1) == NBLK - 1) {
            g_ctr = 0;
            __threadfence();
            g_sense = phase;
        } else {
            while (g_sense != phase) __nanosleep(32);
            __threadfence();
        }
    }
    __syncthreads();
}

// smem carve (floats). P1: refs 0..3072, sel 3072..3136, feat 3200..13920
// P2: Xs 0..512, P 512..8704, RED 12900..12964, INV 13000..13002
// P3: k3 buffers 0..11784, INV preserved at 13000
#define SMF 13952

__global__ __launch_bounds__(512) void uber(
        const float* __restrict__ c,   const float* __restrict__ ct,
        const float* __restrict__ imf,
        const float* __restrict__ wp1, const float* __restrict__ bp1,
        const float* __restrict__ wp2, const float* __restrict__ bp2,
        const float* __restrict__ wc1, const float* __restrict__ bc1,
        const float* __restrict__ wps1, const float* __restrict__ bps1,
        const float* __restrict__ wps2, const float* __restrict__ bps2,
        const float* __restrict__ wc2,  const float* __restrict__ bc2,
        const float* __restrict__ wfc1, const float* __restrict__ bfc1,
        const float* __restrict__ wfc2, const float* __restrict__ bfc2,
        const float* __restrict__ wfc,  const float* __restrict__ bfc,
        float* __restrict__ out) {
    extern __shared__ __align__(16) float sm[];
    int t = threadIdx.x;
    int b = blockIdx.x;
    int p0 = b * 4;

    // ========================= P1 =========================
    if (t < 256) {
        // ---- KNN: 8 queries (warp/query), refs padded to 512 with 1e18 ----
        if (b <= 62) for (int i = t; i < 1536; i += 256) sm[i]        = (i < 1500) ? ct[i] : 1e18f;
        if (b >= 62) for (int i = t; i < 1536; i += 256) sm[1536 + i] = (i < 1500) ? c[i]  : 1e18f;
        BARW(1);

        int warp = t >> 5, lane = t & 31;
        int gw = b * 8 + warp;
        int dir = gw >= NPTS;
        int q = dir ? gw - NPTS : gw;
        const float* Qg = dir ? ct : c;
        float qx = __ldg(Qg + q * 3 + 0), qy = __ldg(Qg + q * 3 + 1), qz = __ldg(Qg + q * 3 + 2);
        float qq = qx * qx + qy * qy + qz * qz;

        const float* R = sm + (dir ? 1536 : 0);
        int j0 = lane * 16;
        float bd[8]; int bi[8];
#pragma unroll
        for (int k = 0; k < 8; k++) { bd[k] = FLT_MAX; bi[k] = 0x3fffffff; }

#pragma unroll
        for (int h8 = 0; h8 < 2; h8++) {
            float f[24];
            const float4* rp = (const float4*)(R + (j0 + h8 * 8) * 3);
#pragma unroll
            for (int v = 0; v < 6; v++) *(float4*)&f[v * 4] = rp[v];
#pragma unroll
            for (int jj = 0; jj < 8; jj++) {
                float rx = f[jj * 3 + 0], ry = f[jj * 3 + 1], rz = f[jj * 3 + 2];
                float d2 = qq - 2.f * (qx * rx + qy * ry + qz * rz) + (rx * rx + ry * ry + rz * rz);
                int j = j0 + h8 * 8 + jj;
                if (d2 < bd[7] || (d2 == bd[7] && j < bi[7])) {
                    bd[7] = d2; bi[7] = j;
#pragma unroll
                    for (int k = 7; k > 0; k--) {
                        if (bd[k] < bd[k - 1] || (bd[k] == bd[k - 1] && bi[k] < bi[k - 1])) {
                            float td = bd[k]; bd[k] = bd[k - 1]; bd[k - 1] = td;
                            int   ti = bi[k]; bi[k] = bi[k - 1]; bi[k - 1] = ti;
                        }
                    }
                }
            }
        }

        int* selS = (int*)(sm + 3072);
#pragma unroll
        for (int s = 0; s < NP; s++) {
            unsigned key = ordf(bd[0]);
            unsigned mk  = __reduce_min_sync(0xffffffffu, key);
            unsigned mask = __ballot_sync(0xffffffffu, key == mk);
            int owner = __ffs(mask) - 1;
            if (lane == owner) {
                selS[warp * 8 + s] = bi[0];
#pragma unroll
                for (int k = 0; k < 7; k++) { bd[k] = bd[k + 1]; bi[k] = bi[k + 1]; }
                bd[7] = FLT_MAX; bi[7] = 0x3fffffff;
            }
        }
        __syncwarp();

        int*   outi = dir ? g_inds_tc : g_inds;
        float* oute = dir ? (g_expw + NCOL) : g_expw;
        float e = 0.f;
        if (lane < NP) {
            int mi = selS[warp * 8 + lane];
            float dx = qx - R[mi * 3 + 0];
            float dy = qy - R[mi * 3 + 1];
            float dz = qz - R[mi * 3 + 2];
            e = expf(-sqrtf(dx * dx + dy * dy + dz * dz));
            outi[q * NP + lane] = mi;
            oute[q * NP + lane] = e;
        }
        // per-query sum of the 8 exp weights (lanes 0-7)
        if (lane < 8) {
            e += __shfl_xor_sync(0x000000ffu, e, 4);
            e += __shfl_xor_sync(0x000000ffu, e, 2);
            e += __shfl_xor_sync(0x000000ffu, e, 1);
            if (lane == 0) g_psum[gw] = e;
        }
    } else {
        // ---- features: 4 points (imf^T, H64, cf, h1) + one transpose tile ----
        int t2 = t - 256;
        float* HS = sm + 3200;           // [4][64]
        float* IS = sm + 3456;           // [4][32]
        float* WC = sm + 3584;           // [32][65]
        float* WT = sm + 5664;           // [64][129]

        for (int e = t2; e < 2048; e += 256) {        // wp2 -> WT[k][r]
            float4 v = __ldg((const float4*)(wp2 + e * 4));
            int r = e >> 4, k0 = (e & 15) * 4;
            WT[(k0 + 0) * 129 + r] = v.x;
            WT[(k0 + 1) * 129 + r] = v.y;
            WT[(k0 + 2) * 129 + r] = v.z;
            WT[(k0 + 3) * 129 + r] = v.w;
        }
        for (int e = t2; e < 512; e += 256) {         // wc1 -> WC[k][r]
            float4 v = __ldg((const float4*)(wc1 + e * 4));
            int r = e >> 3, k0 = (e & 7) * 4;
            WC[(k0 + 0) * 65 + r] = v.x;
            WC[(k0 + 1) * 65 + r] = v.y;
            WC[(k0 + 2) * 65 + r] = v.z;
            WC[(k0 + 3) * 65 + r] = v.w;
        }
        if (t2 < 128) {
            int lp = t2 >> 5, chn = t2 & 31;
            float v = imf[chn * NPTS + (p0 + lp)];
            IS[lp * 32 + chn] = v;
            g_imf[(p0 + lp) * 32 + chn] = v;
        }
        {
            int lp = t2 >> 6, r = t2 & 63;
            int p = p0 + lp;
            float h = bp1[r] + wp1[r * 3 + 0] * c[p * 3 + 0] + wp1[r * 3 + 1] * c[p * 3 + 1]
                             + wp1[r * 3 + 2] * c[p * 3 + 2];
            HS[lp * 64 + r] = lrelu(h);
        }
        BARW(2);

        {   // cf = Wp2 @ H64 + b : thread-per-row x2 cols
            int r = t2 & 127, h = t2 >> 7;
            const float* x0 = HS + (2 * h) * 64;
            const float* x1 = HS + (2 * h + 1) * 64;
            float a0 = 0.f, a1 = 0.f;
#pragma unroll 8
            for (int k = 0; k < 64; k++) {
                float w = WT[k * 129 + r];
                a0 += w * x0[k];
                a1 += w * x1[k];
            }
            float bb = __ldg(bp2 + r);
            g_cf[(p0 + 2 * h) * 128 + r]     = a0 + bb;
            g_cf[(p0 + 2 * h + 1) * 128 + r] = a1 + bb;
        }
        {   // h1 = lrelu(Wc1 @ imf + b)
            int r = t2 & 63, cc = t2 >> 6;
            const float* xi = IS + cc * 32;
            float a = 0.f;
#pragma unroll 8
            for (int k = 0; k < 32; k++) a += WC[k * 65 + r] * xi[k];
            g_h1[(p0 + cc) * 64 + r] = lrelu(a + __ldg(bc1 + r));
        }

        if (b < 106) {   // one 32x32 transpose tile per block
            const float* src; float* dst; int Rr, Cc, tile;
            if      (b < 32)  { src = wps2; dst = g_wps2T; Rr = 128; Cc = 256; tile = b; }
            else if (b < 40)  { src = wc2;  dst = g_wc2T;  Rr = 128; Cc = 64;  tile = b - 32; }
            else if (b < 56)  { src = wfc1; dst = g_wfc1T; Rr = 64;  Cc = 256; tile = b - 40; }
            else if (b < 66)  { src = wfc2; dst = g_wfc2T; Rr = 64;  Cc = 160; tile = b - 56; }
            else if (b < 74)  { src = wfc;  dst = g_wfcT;  Rr = 64;  Cc = 128; tile = b - 66; }
            else              { src = wps1; dst = g_wps1T; Rr = 256; Cc = 128; tile = b - 74; }
            int tilesC = Cc / 32;
            int tr = (tile / tilesC) * 32, tc = (tile % tilesC) * 32;
            float (*S)[33] = (float(*)[33])WT;   // alias (WT dead after cf)
            int r = t2 >> 3, qd = t2 & 7;
            BARW(2);                              // ensure cf readers done with WT
            float4 v = *(const float4*)(src + (tr + r) * Cc + tc + qd * 4);
            S[r][qd * 4 + 0] = v.x; S[r][qd * 4 + 1] = v.y;
            S[r][qd * 4 + 2] = v.z; S[r][qd * 4 + 3] = v.w;
            BARW(2);
            float4 o;
            o.x = S[qd * 4 + 0][r]; o.y = S[qd * 4 + 1][r];
            o.z = S[qd * 4 + 2][r]; o.w = S[qd * 4 + 3][r];
            *(float4*)(dst + (tc + r) * Rr + tr + qd * 4) = o;
        }
    }
    gbar(1);

    // ========================= P2: Hp + denominators =========================
    {
        float* Xs  = sm;          // [4][128]
        float* P2P = sm + 512;    // [32][256]
        float* RED = sm + 12900;  // [2][32]
        // denominators: fixed-tree reduce of g_psum
        {
            float v0 = (t < 500) ? g_psum[t]       : 0.f;
            float v1 = (t < 500) ? g_psum[500 + t] : 0.f;
#pragma unroll
            for (int off = 16; off; off >>= 1) {
                v0 += __shfl_xor_sync(0xffffffffu, v0, off);
                v1 += __shfl_xor_sync(0xffffffffu, v1, off);
            }
            if ((t & 31) == 0) { RED[t >> 5] = v0; RED[32 + (t >> 5)] = v1; }
        }
        if (t < 128) {
            int col = t >> 5, f = t & 31;
            *(float4*)&Xs[col * 128 + f * 4] = *(const float4*)&g_cf[(p0 + col) * 128 + f * 4];
        }
        __syncthreads();
        if (t == 0) {
            float s0 = 0.f, s1 = 0.f;
#pragma unroll
            for (int w = 0; w < 16; w++) { s0 += RED[w]; s1 += RED[32 + w]; }
            sm[13000] = 1.f / s0;
            sm[13001] = 1.f / s1;
        }
        {   // Hp: 256 rows x 4 cols, K=128; rq=t&63, ks=t>>6 (8 x K=16)
            int rq = t & 63, ks = t >> 6;
            float4 a[4] = {};
            const float* wp = g_wps1T + (ks * 16) * 256 + rq * 4;
#pragma unroll
            for (int kg = 0; kg < 4; kg++) {
                float xk[4][4];
#pragma unroll
                for (int cc = 0; cc < 4; cc++)
                    *(float4*)xk[cc] = *(float4*)&Xs[cc * 128 + ks * 16 + kg * 4];
#pragma unroll
                for (int j = 0; j < 4; j++) {
                    float4 w4 = *(const float4*)(wp + (kg * 4 + j) * 256);
#pragma unroll
                    for (int cc = 0; cc < 4; cc++) {
                        float x = xk[cc][j];
                        a[cc].x += w4.x * x; a[cc].y += w4.y * x; a[cc].z += w4.z * x; a[cc].w += w4.w * x;
                    }
                }
            }
#pragma unroll
            for (int cc = 0; cc < 4; cc++)
                *(float4*)&P2P[(ks * 4 + cc) * 256 + rq * 4] = a[cc];
        }
        __syncthreads();
        for (int o = t; o < 1024; o += 512) {
            int r = o & 255, cc = o >> 8;
            float s = 0.f;
#pragma unroll
            for (int ks = 0; ks < 8; ks++) s += P2P[(ks * 4 + cc) * 256 + r];
            g_hp[(p0 + cc) * 256 + r] = lrelu(s + bps1[r]);
        }
    }
    gbar(0);

    // ========================= P3: gathers + GEMM chain =========================
    {
        int*   I0  = (int*)(sm + 0);
        int*   I1  = (int*)(sm + 32);
        float* W0  = sm + 64;
        float* W1  = sm + 96;
        float* Ws0 = sm + 128;
        float* Ws1 = sm + 132;
        float* Hb  = sm + 136;    // [4][64]
        float* Hpb = sm + 392;    // [4][256]
        float* A1  = sm + 1416;   // [4][256]  low=Sf high=Cf
        float* A2  = sm + 2440;   // [4][160]  low=Sfp high=Im
        float* Z   = sm + 3080;   // [4][128]
        float* PA  = sm + 3592;   // 4096
        float* PB  = sm + 7688;   // 4096
        float inv0 = sm[13000], inv1 = sm[13001];

        int wg = t >> 8, ta = t & 255;

        if (wg == 0) {
            if (ta < 32) {
                int e = p0 * NP + ta;
                I0[ta] = g_inds[e];    W0[ta] = g_expw[e];
                I1[ta] = g_inds_tc[e]; W1[ta] = g_expw[NCOL + e];
            } else if (ta < 64) {
                int tt = ta - 32;
                int col = tt >> 3, f = tt & 7;
                *(float4*)&A2[col * 160 + 128 + f * 4] = *(const float4*)&g_imf[(p0 + col) * 32 + f * 4];
            }
        } else {
            if (ta < 128) {
                int col = ta >> 5, f = ta & 31;
                *(float4*)&A1[col * 256 + 128 + f * 4] = *(const float4*)&g_cf[(p0 + col) * 128 + f * 4];
            }
        }
        __syncthreads();

        if (wg == 0) {
            if (ta < 4) {
                float s = 0;
#pragma unroll
                for (int j = 0; j < 8; j++) s += W1[ta * 8 + j];
                Ws1[ta] = 0.125f * inv1 * s;
            }
            {
                int r = ta;
#pragma unroll
                for (int lp = 0; lp < 4; lp++) {
                    float s = 0;
#pragma unroll
                    for (int j = 0; j < 8; j++) s += W1[lp * 8 + j] * g_hp[I1[lp * 8 + j] * 256 + r];
                    Hpb[lp * 256 + r] = 0.125f * inv1 * s;
                }
            }
            BARW(1);
            {   // Y2: 128 rows, K=256
                int rq = ta & 31, ks = ta >> 5;
                float4 a[4] = {};
                const float* wp = g_wps2T + (ks * 32) * 128 + rq * 4;
#pragma unroll
                for (int kg = 0; kg < 8; kg++) {
                    float xk[4][4];
#pragma unroll
                    for (int cc = 0; cc < 4; cc++)
                        *(float4*)xk[cc] = *(float4*)&Hpb[cc * 256 + ks * 32 + kg * 4];
#pragma unroll
                    for (int j = 0; j < 4; j++) {
                        float4 w4 = *(const float4*)(wp + (kg * 4 + j) * 128);
#pragma unroll
                        for (int cc = 0; cc < 4; cc++) {
                            float x = xk[cc][j];
                            a[cc].x += w4.x * x; a[cc].y += w4.y * x; a[cc].z += w4.z * x; a[cc].w += w4.w * x;
                        }
                    }
                }
#pragma unroll
                for (int cc = 0; cc < 4; cc++)
                    *(float4*)&PA[(ks * 4 + cc) * 128 + rq * 4] = a[cc];
            }
            BARW(1);
            for (int o = ta; o < 512; o += 256) {
                int r = o & 127, cc = o >> 7;
                float s = 0;
#pragma unroll
                for (int ks = 0; ks < 8; ks++) s += PA[(ks * 4 + cc) * 128 + r];
                A2[cc * 160 + r] = s + bps2[r] * Ws1[cc];
            }
            BARW(1);
            {   // f2: 64 rows, K=160
                int rq = ta & 15, ks = ta >> 4;
                float4 a[4] = {};
                const float* wp = g_wfc2T + (ks * 10) * 64 + rq * 4;
#pragma unroll
                for (int k = 0; k < 10; k++) {
                    float4 w4 = *(const float4*)(wp + k * 64);
                    int kk = ks * 10 + k;
#pragma unroll
                    for (int cc = 0; cc < 4; cc++) {
                        float x = A2[cc * 160 + kk];
                        a[cc].x += w4.x * x; a[cc].y += w4.y * x; a[cc].z += w4.z * x; a[cc].w += w4.w * x;
                    }
                }
#pragma unroll
                for (int cc = 0; cc < 4; cc++)
                    *(float4*)&PA[(ks * 4 + cc) * 64 + rq * 4] = a[cc];
            }
            BARW(1);
            {
                int ch = ta & 63, cc = ta >> 6;
                float s = 0;
#pragma unroll
                for (int ks = 0; ks < 16; ks++) s += PA[(ks * 4 + cc) * 64 + ch];
                Z[cc * 128 + ch] = lrelu(s + bfc2[ch]);
            }
        } else {
            if (ta < 4) {
                float s = 0;
#pragma unroll
                for (int j = 0; j < 8; j++) s += W0[ta * 8 + j];
                Ws0[ta] = 0.125f * inv0 * s;
            }
            {
                int lp = ta >> 6, r = ta & 63;
                float s = 0;
#pragma unroll
                for (int j = 0; j < 8; j++) s += W0[lp * 8 + j] * g_h1[I0[lp * 8 + j] * 64 + r];
                Hb[lp * 64 + r] = 0.125f * inv0 * s;
            }
            BARW(2);
            {   // Y1: 128 rows, K=64
                int rq = ta & 31, ks = ta >> 5;
                float4 a[4] = {};
                const float* wp = g_wc2T + (ks * 8) * 128 + rq * 4;
#pragma unroll
                for (int kg = 0; kg < 2; kg++) {
                    float xk[4][4];
#pragma unroll
                    for (int cc = 0; cc < 4; cc++)
                        *(float4*)xk[cc] = *(float4*)&Hb[cc * 64 + ks * 8 + kg * 4];
#pragma unroll
                    for (int j = 0; j < 4; j++) {
                        float4 w4 = *(const float4*)(wp + (kg * 4 + j) * 128);
#pragma unroll
                        for (int cc = 0; cc < 4; cc++) {
                            float x = xk[cc][j];
                            a[cc].x += w4.x * x; a[cc].y += w4.y * x; a[cc].z += w4.z * x; a[cc].w += w4.w * x;
                        }
                    }
                }
#pragma unroll
                for (int cc = 0; cc < 4; cc++)
                    *(float4*)&PB[(ks * 4 + cc) * 128 + rq * 4] = a[cc];
            }
            BARW(2);
            for (int o = ta; o < 512; o += 256) {
                int r = o & 127, cc = o >> 7;
                float s = 0;
#pragma unroll
                for (int ks = 0; ks < 8; ks++) s += PB[(ks * 4 + cc) * 128 + r];
                A1[cc * 256 + r] = s + bc2[r] * Ws0[cc];
            }
            BARW(2);
            {   // f1: 64 rows, K=256
                int rq = ta & 15, ks = ta >> 4;
                float4 a[4] = {};
                const float* wp = g_wfc1T + (ks * 16) * 64 + rq * 4;
#pragma unroll
                for (int kg = 0; kg < 4; kg++) {
                    float xk[4][4];
#pragma unroll
                    for (int cc = 0; cc < 4; cc++)
                        *(float4*)xk[cc] = *(float4*)&A1[cc * 256 + ks * 16 + kg * 4];
#pragma unroll
                    for (int j = 0; j < 4; j++) {
                        float4 w4 = *(const float4*)(wp + (kg * 4 + j) * 64);
#pragma unroll
                        for (int cc = 0; cc < 4; cc++) {
                            float x = xk[cc][j];
                            a[cc].x += w4.x * x; a[cc].y += w4.y * x; a[cc].z += w4.z * x; a[cc].w += w4.w * x;
                        }
                    }
                }
#pragma unroll
                for (int cc = 0; cc < 4; cc++)
                    *(float4*)&PB[(ks * 4 + cc) * 64 + rq * 4] = a[cc];
            }
            BARW(2);
            {
                int ch = ta & 63, cc = ta >> 6;
                float s = 0;
#pragma unroll
                for (int ks = 0; ks < 16; ks++) s += PB[(ks * 4 + cc) * 64 + ch];
                Z[cc * 128 + 64 + ch] = lrelu(s + bfc1[ch]);
            }
        }
        __syncthreads();

        if (wg == 0) {
            {   // out: 64 rows, K=128
                int rq = ta & 15, ks = ta >> 4;
                float4 a[4] = {};
                const float* wp = g_wfcT + (ks * 8) * 64 + rq * 4;
#pragma unroll
                for (int kg = 0; kg < 2; kg++) {
                    float xk[4][4];
#pragma unroll
                    for (int cc = 0; cc < 4; cc++)
                        *(float4*)xk[cc] = *(float4*)&Z[cc * 128 + ks * 8 + kg * 4];
#pragma unroll
                    for (int j = 0; j < 4; j++) {
                        float4 w4 = *(const float4*)(wp + (kg * 4 + j) * 64);
#pragma unroll
                        for (int cc = 0; cc < 4; cc++) {
                            float x = xk[cc][j];
                            a[cc].x += w4.x * x; a[cc].y += w4.y * x; a[cc].z += w4.z * x; a[cc].w += w4.w * x;
                        }
                    }
                }
#pragma unroll
                for (int cc = 0; cc < 4; cc++)
                    *(float4*)&PA[(ks * 4 + cc) * 64 + rq * 4] = a[cc];
            }
            BARW(1);
            {
                int ch = ta & 63, cc = ta >> 6;
                float s = 0;
#pragma unroll
                for (int ks = 0; ks < 16; ks++) s += PA[(ks * 4 + cc) * 64 + ch];
                out[ch * NPTS + (p0 + cc)] = s + bfc[ch];
            }
        }
    }
}

// ---------------- launch ----------------
extern "C" void kernel_launch(void* const* d_in, const int* in_sizes, int n_in,
                              void* d_out, int out_size) {
    const float* imf   = (const float*)d_in[0];
    const float* cloud = (const float*)d_in[1];
    const float* ctar  = (const float*)d_in[2];
    const float* w_conv1   = (const float*)d_in[3];
    const float* b_conv1   = (const float*)d_in[4];
    const float* w_conv2   = (const float*)d_in[5];
    const float* b_conv2   = (const float*)d_in[6];
    const float* w_psconv1 = (const float*)d_in[7];
    const float* b_psconv1 = (const float*)d_in[8];
    const float* w_psconv2 = (const float*)d_in[9];
    const float* b_psconv2 = (const float*)d_in[10];
    const float* w_pconv1  = (const float*)d_in[11];
    const float* b_pconv1  = (const float*)d_in[12];
    const float* w_pconv2  = (const float*)d_in[13];
    const float* b_pconv2  = (const float*)d_in[14];
    const float* w_fc1 = (const float*)d_in[15];
    const float* b_fc1 = (const float*)d_in[16];
    const float* w_fc2 = (const float*)d_in[17];
    const float* b_fc2 = (const float*)d_in[18];
    const float* w_fc  = (const float*)d_in[19];
    const float* b_fc  = (const float*)d_in[20];
    float* out = (float*)d_out;

    static bool attr_set = false;
    if (!attr_set) {
        cudaFuncSetAttribute(uber, cudaFuncAttributeMaxDynamicSharedMemorySize, SMF * 4);
        attr_set = true;
    }
    uber<<<NBLK, 512, SMF * 4>>>(cloud, ctar, imf,
                                 w_pconv1, b_pconv1, w_pconv2, b_pconv2,
                                 w_conv1, b_conv1,
                                 w_psconv1, b_psconv1,
                                 w_psconv2, b_psconv2,
                                 w_conv2, b_conv2,
                                 w_fc1, b_fc1, w_fc2, b_fc2, w_fc, b_fc,
                                 out);
}